// round 8
// baseline (speedup 1.0000x reference)
#include <cuda_runtime.h>
#include <cuda_fp16.h>
#include <math.h>
#include <stdint.h>

#define CN 131072
#define CE 524288
#define CG 4096
#define DIN 128
#define DH  512
#define DOUTD 256
#define BN_EPS 1e-5f

// ---------------- scratch (static device globals; no allocation) -------------
__device__ float g_dinv[CN];
__device__ int   g_cnt [CN];
__device__ int   g_noff[CN + 1];
__device__ int   g_cur [CN];
__device__ int   g_bsum[512];
__device__ int   g_csrc[CE];
__device__ float g_cw  [CE];
__device__ int   g_gcnt[CG];
__device__ int   g_goff[CG + 1];
__device__ int   g_gbsum[16];
__device__ float g_bns [DH + DOUTD];
__device__ float g_bnsh[DH + DOUTD];
__device__ __half g_agg1[(size_t)CN * DIN];     // GEMM1 A (fp16)
__device__ __half g_h1  [(size_t)CN * DH];      // GEMM2 A (fp16)
__device__ __half g_t2  [(size_t)CN * DH];      // GEMM2 out (fp16, gathered)
__device__ __half g_a2  [(size_t)CN * DH];      // GEMM3 A (fp16)
__device__ __half g_t3  [(size_t)CN * DOUTD];   // GEMM3 out (fp16, gathered)
__device__ float  g_a3  [(size_t)CN * DOUTD];   // pooled input (fp32)
__device__ __half g_pool[(size_t)CG * DOUTD];   // head GEMM1 A (fp16)
__device__ __half g_mlp1[(size_t)CG * DOUTD];   // head GEMM2 A (fp16)
// fp16 k-pair-packed weights: Wp[k2*N + n] = half2(W[2k2][n], W[2k2+1][n])
__device__ uint32_t g_wp1 [(DIN / 2) * DH];
__device__ uint32_t g_wp2 [(DH / 2) * DH];
__device__ uint32_t g_wp3 [(DH / 2) * DOUTD];
__device__ uint32_t g_wpf1[(DOUTD / 2) * DOUTD];
__device__ uint32_t g_wpf2[(DOUTD / 2) * DOUTD];

// ---------------- small utility kernels --------------------------------------
__global__ void k_zero_i(int* __restrict__ p, int n) {
    unsigned i = blockIdx.x * blockDim.x + threadIdx.x;
    if (i < (unsigned)n) p[i] = 0;
}

__global__ void k_hist(const int* __restrict__ keys, int n, int* __restrict__ cnt) {
    unsigned i = blockIdx.x * blockDim.x + threadIdx.x;
    if (i < (unsigned)n) atomicAdd(&cnt[keys[i]], 1);
}

__global__ void k_dinv_from_cnt(const int* __restrict__ cnt, float* __restrict__ dinv) {
    unsigned i = blockIdx.x * blockDim.x + threadIdx.x;
    if (i < CN) dinv[i] = rsqrtf((float)(cnt[i] + 1));
}

__global__ void k_scan_block(const int* __restrict__ in, int* __restrict__ out,
                             int* __restrict__ bsum, int n) {
    __shared__ int sh[256];
    int t = threadIdx.x;
    int i = blockIdx.x * 256 + t;
    int v = (i < n) ? in[i] : 0;
    sh[t] = v; __syncthreads();
#pragma unroll
    for (int o = 1; o < 256; o <<= 1) {
        int x = (t >= o) ? sh[t - o] : 0;
        __syncthreads();
        sh[t] += x;
        __syncthreads();
    }
    if (i < n) out[i] = sh[t] - v;
    if (t == 255) bsum[blockIdx.x] = sh[255];
}

__global__ void k_scan_partials(int* __restrict__ bsum, int nb) {
    __shared__ int sh[1024];
    int t = threadIdx.x;
    int v = (t < nb) ? bsum[t] : 0;
    sh[t] = v; __syncthreads();
#pragma unroll
    for (int o = 1; o < 1024; o <<= 1) {
        int x = (t >= o) ? sh[t - o] : 0;
        __syncthreads();
        sh[t] += x;
        __syncthreads();
    }
    if (t < nb) bsum[t] = sh[t] - v;
}

__global__ void k_scan_add(int* __restrict__ out, const int* __restrict__ bsum,
                           int n, int total) {
    unsigned i = blockIdx.x * blockDim.x + threadIdx.x;
    if (i < (unsigned)n) out[i] += bsum[i >> 8];
    if (i == 0) out[n] = total;
}

__global__ void k_csr_scatter(const int* __restrict__ src, const int* __restrict__ dst,
                              const float* __restrict__ dinv,
                              const int* __restrict__ noff, int* __restrict__ cur,
                              int* __restrict__ csrc, float* __restrict__ cw) {
    unsigned e = blockIdx.x * blockDim.x + threadIdx.x;
    if (e >= CE) return;
    int d = dst[e], s = src[e];
    int pos = noff[d] + atomicAdd(&cur[d], 1);
    csrc[pos] = s;
    cw[pos] = dinv[s] * dinv[d];
}

__global__ void k_bnprep(const float* __restrict__ g, const float* __restrict__ be,
                         const float* __restrict__ m, const float* __restrict__ v,
                         float* __restrict__ s, float* __restrict__ sh, int n) {
    unsigned i = blockIdx.x * blockDim.x + threadIdx.x;
    if (i >= (unsigned)n) return;
    float sc = g[i] * rsqrtf(v[i] + BN_EPS);
    s[i] = sc;
    sh[i] = be[i] - m[i] * sc;
}

// pack W[K,N] fp32 -> Wp[K/2, N] uint32 (half2 over adjacent k)
__global__ void k_wpack(const float* __restrict__ W, uint32_t* __restrict__ Wp,
                        int K, int N) {
    unsigned i = blockIdx.x * blockDim.x + threadIdx.x;
    if (i >= (unsigned)((K / 2) * N)) return;
    int k2 = i / N, n = i % N;
    __half2 h = __floats2half2_rn(W[(size_t)(2 * k2) * N + n],
                                  W[(size_t)(2 * k2 + 1) * N + n]);
    Wp[i] = *reinterpret_cast<uint32_t*>(&h);
}

// ---------------- CSR aggregation: fp32 input (layer 1 only) ------------------
__global__ __launch_bounds__(128) void k_agg_csr_f(
    const float* __restrict__ t, __half* __restrict__ out,
    const int* __restrict__ noff, const int* __restrict__ csrc,
    const float* __restrict__ cw, const float* __restrict__ dinv) {
    constexpr int D = DIN;
    constexpr int TPN = D / 4;        // 32
    constexpr int NPB = 128 / TPN;    // 4
    int node = blockIdx.x * NPB + threadIdx.x / TPN;
    int lane = threadIdx.x % TPN;
    int c = lane * 4;

    float di = dinv[node];
    float4 acc = *reinterpret_cast<const float4*>(t + (size_t)node * D + c);
    float w0 = di * di;
    acc.x *= w0; acc.y *= w0; acc.z *= w0; acc.w *= w0;

    int beg = noff[node], end = noff[node + 1];
    for (int p = beg; p < end; p++) {
        int s = csrc[p];
        float w = cw[p];
        float4 v = *reinterpret_cast<const float4*>(t + (size_t)s * D + c);
        acc.x += v.x * w; acc.y += v.y * w; acc.z += v.z * w; acc.w += v.w * w;
    }
    __half2* op = reinterpret_cast<__half2*>(out + (size_t)node * D + c);
    op[0] = __floats2half2_rn(acc.x, acc.y);
    op[1] = __floats2half2_rn(acc.z, acc.w);
}

// ---------------- CSR aggregation: fp16 input (layers 2,3) --------------------
// 8 halves per thread (uint4), fp32 accumulation, fused bias+relu+BN.
// OH: fp16 output; else fp32.
template <int D, bool OH>
__global__ __launch_bounds__(128) void k_agg_csr_h(
    const __half* __restrict__ t, void* __restrict__ out,
    const int* __restrict__ noff, const int* __restrict__ csrc,
    const float* __restrict__ cw, const float* __restrict__ dinv,
    const float* __restrict__ bias, const float* __restrict__ bns,
    const float* __restrict__ bnsh) {
    constexpr int TPN = D / 8;
    constexpr int NPB = 128 / TPN;
    int node = blockIdx.x * NPB + threadIdx.x / TPN;
    int lane = threadIdx.x % TPN;
    int c = lane * 8;

    float di = dinv[node];
    float w0 = di * di;
    float acc[8];
    {
        const __half2* ip = reinterpret_cast<const __half2*>(t + (size_t)node * D + c);
#pragma unroll
        for (int j = 0; j < 4; j++) {
            float2 f = __half22float2(ip[j]);
            acc[2 * j] = f.x * w0;
            acc[2 * j + 1] = f.y * w0;
        }
    }

    int beg = noff[node], end = noff[node + 1];
    for (int p = beg; p < end; p++) {
        int s = csrc[p];
        float w = cw[p];
        uint4 raw = *reinterpret_cast<const uint4*>(t + (size_t)s * D + c);
        const __half2* hp = reinterpret_cast<const __half2*>(&raw);
#pragma unroll
        for (int j = 0; j < 4; j++) {
            float2 f = __half22float2(hp[j]);
            acc[2 * j] += f.x * w;
            acc[2 * j + 1] += f.y * w;
        }
    }

    float vo[8];
#pragma unroll
    for (int j = 0; j < 8; j++) {
        float v = fmaxf(acc[j] + bias[c + j], 0.0f);
        vo[j] = v * bns[c + j] + bnsh[c + j];
    }
    if (OH) {
        __half2 hv[4];
#pragma unroll
        for (int j = 0; j < 4; j++) hv[j] = __floats2half2_rn(vo[2 * j], vo[2 * j + 1]);
        *reinterpret_cast<uint4*>((__half*)out + (size_t)node * D + c) =
            *reinterpret_cast<uint4*>(hv);
    } else {
        float* op = (float*)out + (size_t)node * D + c;
        *reinterpret_cast<float4*>(op) = make_float4(vo[0], vo[1], vo[2], vo[3]);
        *reinterpret_cast<float4*>(op + 4) = make_float4(vo[4], vo[5], vo[6], vo[7]);
    }
}

// ---------------- segment mean pool (fp32 in, fp16 out) -----------------------
__global__ __launch_bounds__(128) void k_pool_seg(const float* __restrict__ h,
                                                  const int* __restrict__ goff,
                                                  __half* __restrict__ pooled) {
    int g = blockIdx.x * 2 + threadIdx.x / 64;
    int lane = threadIdx.x % 64;
    int c = lane * 4;
    int beg = goff[g], end = goff[g + 1];
    float4 acc = make_float4(0.f, 0.f, 0.f, 0.f);
    for (int n = beg; n < end; n++) {
        float4 v = *reinterpret_cast<const float4*>(h + (size_t)n * DOUTD + c);
        acc.x += v.x; acc.y += v.y; acc.z += v.z; acc.w += v.w;
    }
    float inv = 1.0f / fmaxf((float)(end - beg), 1.0f);
    __half2* op = reinterpret_cast<__half2*>(pooled + (size_t)g * DOUTD + c);
    op[0] = __floats2half2_rn(acc.x * inv, acc.y * inv);
    op[1] = __floats2half2_rn(acc.z * inv, acc.w * inv);
}

// ---------------- FP16 tensor-core GEMM (double-buffered) ---------------------
__device__ __forceinline__ void mma_f16(float* c, const uint32_t* a, const uint32_t* b) {
    asm volatile(
        "mma.sync.aligned.m16n8k16.row.col.f32.f16.f16.f32 "
        "{%0,%1,%2,%3}, {%4,%5,%6,%7}, {%8,%9}, {%0,%1,%2,%3};"
        : "+f"(c[0]), "+f"(c[1]), "+f"(c[2]), "+f"(c[3])
        : "r"(a[0]), "r"(a[1]), "r"(a[2]), "r"(a[3]), "r"(b[0]), "r"(b[1]));
}

#define GSTRIDE 136

// EPI: 0=none, 1=bias+relu+BN, 2=bias+relu, 3=bias ; OH: fp16 output
template <int EPI, bool OH>
__global__ __launch_bounds__(256, 2) void k_hgemm(
    const __half* __restrict__ A, const uint32_t* __restrict__ Wp, void* __restrict__ C,
    int M, int K, int Nn,
    const float* __restrict__ bias, const float* __restrict__ bns,
    const float* __restrict__ bnsh) {
    __shared__ uint32_t As[2][16][GSTRIDE];   // [buf][k2][m]
    __shared__ uint32_t Bs[2][16][GSTRIDE];   // [buf][k2][n]

    const int tid = threadIdx.x;
    const int bc = blockIdx.x, br = blockIdx.y;
    const int lane = tid & 31;
    const int wid = tid >> 5;
    const int wm = (wid >> 2) * 64;
    const int wn = (wid & 3) * 32;

    const int arow = tid >> 1;
    const int ak2 = (tid & 1) * 8;
    const int bn4 = (tid & 31) * 4;
    const int brow = tid >> 5;

    const int K2 = K >> 1;
    const uint32_t* Aptr = reinterpret_cast<const uint32_t*>(A)
                           + (size_t)(br * 128 + arow) * K2 + ak2;
    const uint32_t* Bptr = Wp + (size_t)brow * Nn + bc * 128 + bn4;
    const size_t BchunkStep = (size_t)16 * Nn;

    float acc[4][4][4];
#pragma unroll
    for (int mf = 0; mf < 4; mf++)
#pragma unroll
        for (int nf = 0; nf < 4; nf++)
#pragma unroll
            for (int r = 0; r < 4; r++) acc[mf][nf][r] = 0.0f;

    const int nchunks = K >> 5;

    uint4 ra0, ra1, rb0, rb1;
    ra0 = *reinterpret_cast<const uint4*>(Aptr);
    ra1 = *reinterpret_cast<const uint4*>(Aptr + 4);
    rb0 = *reinterpret_cast<const uint4*>(Bptr);
    rb1 = *reinterpret_cast<const uint4*>(Bptr + 8 * Nn);
    {
        As[0][ak2 + 0][arow] = ra0.x; As[0][ak2 + 1][arow] = ra0.y;
        As[0][ak2 + 2][arow] = ra0.z; As[0][ak2 + 3][arow] = ra0.w;
        As[0][ak2 + 4][arow] = ra1.x; As[0][ak2 + 5][arow] = ra1.y;
        As[0][ak2 + 6][arow] = ra1.z; As[0][ak2 + 7][arow] = ra1.w;
        *reinterpret_cast<uint4*>(&Bs[0][brow][bn4]) = rb0;
        *reinterpret_cast<uint4*>(&Bs[0][brow + 8][bn4]) = rb1;
    }
    __syncthreads();

    const int gr = lane >> 2;
    const int gc = lane & 3;

    for (int i = 0; i < nchunks; i++) {
        if (i + 1 < nchunks) {
            const uint32_t* Ap = Aptr + (i + 1) * 16;
            const uint32_t* Bp = Bptr + (size_t)(i + 1) * BchunkStep;
            ra0 = *reinterpret_cast<const uint4*>(Ap);
            ra1 = *reinterpret_cast<const uint4*>(Ap + 4);
            rb0 = *reinterpret_cast<const uint4*>(Bp);
            rb1 = *reinterpret_cast<const uint4*>(Bp + 8 * Nn);
        }

        const int cb = i & 1;
#pragma unroll
        for (int ks2 = 0; ks2 < 16; ks2 += 8) {
            uint32_t af[4][4];
#pragma unroll
            for (int mf = 0; mf < 4; mf++) {
                int mb = wm + mf * 16;
                af[mf][0] = As[cb][ks2 + gc][mb + gr];
                af[mf][1] = As[cb][ks2 + gc][mb + gr + 8];
                af[mf][2] = As[cb][ks2 + gc + 4][mb + gr];
                af[mf][3] = As[cb][ks2 + gc + 4][mb + gr + 8];
            }
            uint32_t bf[4][2];
#pragma unroll
            for (int nf = 0; nf < 4; nf++) {
                int nb = wn + nf * 8;
                bf[nf][0] = Bs[cb][ks2 + gc][nb + gr];
                bf[nf][1] = Bs[cb][ks2 + gc + 4][nb + gr];
            }
#pragma unroll
            for (int mf = 0; mf < 4; mf++)
#pragma unroll
                for (int nf = 0; nf < 4; nf++)
                    mma_f16(acc[mf][nf], af[mf], bf[nf]);
        }

        if (i + 1 < nchunks) {
            const int nb2 = (i + 1) & 1;
            As[nb2][ak2 + 0][arow] = ra0.x; As[nb2][ak2 + 1][arow] = ra0.y;
            As[nb2][ak2 + 2][arow] = ra0.z; As[nb2][ak2 + 3][arow] = ra0.w;
            As[nb2][ak2 + 4][arow] = ra1.x; As[nb2][ak2 + 5][arow] = ra1.y;
            As[nb2][ak2 + 6][arow] = ra1.z; As[nb2][ak2 + 7][arow] = ra1.w;
            *reinterpret_cast<uint4*>(&Bs[nb2][brow][bn4]) = rb0;
            *reinterpret_cast<uint4*>(&Bs[nb2][brow + 8][bn4]) = rb1;
        }
        __syncthreads();
    }

    float* Cf = reinterpret_cast<float*>(C);
    __half* Ch = reinterpret_cast<__half*>(C);
#pragma unroll
    for (int nf = 0; nf < 4; nf++) {
        int col = bc * 128 + wn + nf * 8 + gc * 2;
        float bb0 = 0.f, bb1 = 0.f, s0 = 1.f, s1 = 1.f, h0 = 0.f, h1 = 0.f;
        if (EPI != 0) { bb0 = bias[col]; bb1 = bias[col + 1]; }
        if (EPI == 1) {
            s0 = bns[col]; s1 = bns[col + 1];
            h0 = bnsh[col]; h1 = bnsh[col + 1];
        }
#pragma unroll
        for (int mf = 0; mf < 4; mf++) {
            int row0 = br * 128 + wm + mf * 16 + gr;
            float v0 = acc[mf][nf][0], v1 = acc[mf][nf][1];
            float v2 = acc[mf][nf][2], v3 = acc[mf][nf][3];
            if (EPI != 0) { v0 += bb0; v1 += bb1; v2 += bb0; v3 += bb1; }
            if (EPI == 1 || EPI == 2) {
                v0 = fmaxf(v0, 0.f); v1 = fmaxf(v1, 0.f);
                v2 = fmaxf(v2, 0.f); v3 = fmaxf(v3, 0.f);
            }
            if (EPI == 1) {
                v0 = v0 * s0 + h0; v1 = v1 * s1 + h1;
                v2 = v2 * s0 + h0; v3 = v3 * s1 + h1;
            }
            if (OH) {
                *reinterpret_cast<__half2*>(Ch + (size_t)row0 * Nn + col) =
                    __floats2half2_rn(v0, v1);
                *reinterpret_cast<__half2*>(Ch + (size_t)(row0 + 8) * Nn + col) =
                    __floats2half2_rn(v2, v3);
            } else {
                *reinterpret_cast<float2*>(Cf + (size_t)row0 * Nn + col) = make_float2(v0, v1);
                *reinterpret_cast<float2*>(Cf + (size_t)(row0 + 8) * Nn + col) = make_float2(v2, v3);
            }
        }
    }
}

// ---------------- launch -----------------------------------------------------
extern "C" void kernel_launch(void* const* d_in, const int* in_sizes, int n_in,
                              void* d_out, int out_size) {
    const float* x   = (const float*)d_in[0];
    const int* ei    = (const int*)d_in[1];
    const int* batch = (const int*)d_in[2];
    const float* W1  = (const float*)d_in[3];  const float* b1  = (const float*)d_in[4];
    const float* W2  = (const float*)d_in[5];  const float* b2  = (const float*)d_in[6];
    const float* W3  = (const float*)d_in[7];  const float* b3  = (const float*)d_in[8];
    const float* g1  = (const float*)d_in[9];  const float* be1 = (const float*)d_in[10];
    const float* m1  = (const float*)d_in[11]; const float* v1  = (const float*)d_in[12];
    const float* g2  = (const float*)d_in[13]; const float* be2 = (const float*)d_in[14];
    const float* m2  = (const float*)d_in[15]; const float* v2  = (const float*)d_in[16];
    const float* g3  = (const float*)d_in[17]; const float* be3 = (const float*)d_in[18];
    const float* m3  = (const float*)d_in[19]; const float* v3  = (const float*)d_in[20];
    const float* Wf1 = (const float*)d_in[21]; const float* bf1 = (const float*)d_in[22];
    const float* Wf2 = (const float*)d_in[23]; const float* bf2 = (const float*)d_in[24];
    float* out = (float*)d_out;

    const int* src = ei;
    const int* dst = ei + CE;

    float *dinv, *cw, *a3, *bns, *bnsh;
    __half *agg1, *h1, *t2, *a2, *t3, *pool, *mlp1;
    uint32_t *wp1, *wp2, *wp3, *wpf1, *wpf2;
    int *cnt, *noff, *cur, *bsum, *csrc, *gcnt, *goff, *gbsum;
    cudaGetSymbolAddress((void**)&dinv, g_dinv);
    cudaGetSymbolAddress((void**)&cnt,  g_cnt);
    cudaGetSymbolAddress((void**)&noff, g_noff);
    cudaGetSymbolAddress((void**)&cur,  g_cur);
    cudaGetSymbolAddress((void**)&bsum, g_bsum);
    cudaGetSymbolAddress((void**)&csrc, g_csrc);
    cudaGetSymbolAddress((void**)&cw,   g_cw);
    cudaGetSymbolAddress((void**)&gcnt, g_gcnt);
    cudaGetSymbolAddress((void**)&goff, g_goff);
    cudaGetSymbolAddress((void**)&gbsum, g_gbsum);
    cudaGetSymbolAddress((void**)&bns,  g_bns);
    cudaGetSymbolAddress((void**)&bnsh, g_bnsh);
    cudaGetSymbolAddress((void**)&agg1, g_agg1);
    cudaGetSymbolAddress((void**)&h1,   g_h1);
    cudaGetSymbolAddress((void**)&t2,   g_t2);
    cudaGetSymbolAddress((void**)&a2,   g_a2);
    cudaGetSymbolAddress((void**)&t3,   g_t3);
    cudaGetSymbolAddress((void**)&a3,   g_a3);
    cudaGetSymbolAddress((void**)&pool, g_pool);
    cudaGetSymbolAddress((void**)&mlp1, g_mlp1);
    cudaGetSymbolAddress((void**)&wp1,  g_wp1);
    cudaGetSymbolAddress((void**)&wp2,  g_wp2);
    cudaGetSymbolAddress((void**)&wp3,  g_wp3);
    cudaGetSymbolAddress((void**)&wpf1, g_wpf1);
    cudaGetSymbolAddress((void**)&wpf2, g_wpf2);

    const int T = 256;

    // ---- pack weights to fp16 ----
    k_wpack<<<((DIN / 2) * DH + T - 1) / T, T>>>(W1, wp1, DIN, DH);
    k_wpack<<<((DH / 2) * DH + T - 1) / T, T>>>(W2, wp2, DH, DH);
    k_wpack<<<((DH / 2) * DOUTD + T - 1) / T, T>>>(W3, wp3, DH, DOUTD);
    k_wpack<<<((DOUTD / 2) * DOUTD + T - 1) / T, T>>>(Wf1, wpf1, DOUTD, DOUTD);
    k_wpack<<<((DOUTD / 2) * DOUTD + T - 1) / T, T>>>(Wf2, wpf2, DOUTD, DOUTD);

    // ---- CSR build ----
    k_zero_i<<<(CN + T - 1) / T, T>>>(cnt, CN);
    k_zero_i<<<(CN + T - 1) / T, T>>>(cur, CN);
    k_zero_i<<<(CG + T - 1) / T, T>>>(gcnt, CG);
    k_hist<<<(CE + T - 1) / T, T>>>(dst, CE, cnt);
    k_hist<<<(CN + T - 1) / T, T>>>(batch, CN, gcnt);
    k_dinv_from_cnt<<<(CN + T - 1) / T, T>>>(cnt, dinv);
    k_scan_block<<<CN / 256, 256>>>(cnt, noff, bsum, CN);
    k_scan_partials<<<1, 1024>>>(bsum, CN / 256);
    k_scan_add<<<(CN + T - 1) / T, T>>>(noff, bsum, CN, CE);
    k_scan_block<<<CG / 256, 256>>>(gcnt, goff, gbsum, CG);
    k_scan_partials<<<1, 1024>>>(gbsum, CG / 256);
    k_scan_add<<<(CG + T - 1) / T, T>>>(goff, gbsum, CG, CN);
    k_csr_scatter<<<(CE + T - 1) / T, T>>>(src, dst, dinv, noff, cur, csrc, cw);

    // ---- layer1 BN consts ----
    k_bnprep<<<(DH + T - 1) / T, T>>>(g1, be1, m1, v1, bns, bnsh, DH);

    // ---- layer 1: aggregate (fp32 in, fp16 out) then GEMM (bias+relu+BN) ----
    k_agg_csr_f<<<CN / 4, 128>>>(x, agg1, noff, csrc, cw, dinv);
    {
        dim3 grid(DH / 128, CN / 128);
        k_hgemm<1, true><<<grid, 256>>>(agg1, wp1, h1, CN, DIN, DH, b1, bns, bnsh);
    }

    // re-prep BN consts for layers 2 & 3
    k_bnprep<<<(DH + T - 1) / T, T>>>(g2, be2, m2, v2, bns, bnsh, DH);
    k_bnprep<<<(DOUTD + T - 1) / T, T>>>(g3, be3, m3, v3, bns + DH, bnsh + DH, DOUTD);

    // ---- layer 2: GEMM (fp16 out) then aggregate (fp16 in, fp16 out) ----
    {
        dim3 grid(DH / 128, CN / 128);
        k_hgemm<0, true><<<grid, 256>>>(h1, wp2, t2, CN, DH, DH, nullptr, nullptr, nullptr);
    }
    k_agg_csr_h<DH, true><<<CN / 2, 128>>>(t2, a2, noff, csrc, cw, dinv, b2, bns, bnsh);

    // ---- layer 3: GEMM (fp16 out) then aggregate (fp16 in, fp32 out) ----
    {
        dim3 grid(DOUTD / 128, CN / 128);
        k_hgemm<0, true><<<grid, 256>>>(a2, wp3, t3, CN, DH, DOUTD, nullptr, nullptr, nullptr);
    }
    k_agg_csr_h<DOUTD, false><<<CN / 4, 128>>>(t3, a3, noff, csrc, cw, dinv,
                                               b3, bns + DH, bnsh + DH);

    // ---- segment mean pool (fp16 out) ----
    k_pool_seg<<<CG / 2, 128>>>(a3, goff, pool);

    // ---- MLP head ----
    {
        dim3 grid(DOUTD / 128, CG / 128);
        k_hgemm<2, true><<<grid, 256>>>(pool, wpf1, mlp1, CG, DOUTD, DOUTD, bf1, nullptr, nullptr);
        k_hgemm<3, false><<<grid, 256>>>(mlp1, wpf2, out, CG, DOUTD, DOUTD, bf2, nullptr, nullptr);
    }
}

// round 10
// speedup vs baseline: 1.0498x; 1.0498x over previous
#include <cuda_runtime.h>
#include <cuda_fp16.h>
#include <math.h>
#include <stdint.h>

#define CN 131072
#define CE 524288
#define CG 4096
#define DIN 128
#define DH  512
#define DOUTD 256
#define BN_EPS 1e-5f

// ---------------- scratch (static device globals; no allocation) -------------
__device__ float g_dinv[CN];
__device__ int   g_cnt [CN];
__device__ int   g_noff[CN + 1];
__device__ int   g_cur [CN];
__device__ int   g_bsum[512];
__device__ int   g_csrc[CE];
__device__ float g_cw  [CE];
__device__ int   g_gcnt[CG];
__device__ int   g_goff[CG + 1];
__device__ int   g_gbsum[16];
__device__ float g_bns [DH + DOUTD];
__device__ float g_bnsh[DH + DOUTD];
__device__ __half g_agg1[(size_t)CN * DIN];     // GEMM1 A (fp16)
__device__ __half g_h1  [(size_t)CN * DH];      // GEMM2 A (fp16)
__device__ float  g_t2  [(size_t)CN * DH];      // GEMM2 out (fp32, gathered)
__device__ __half g_a2  [(size_t)CN * DH];      // GEMM3 A (fp16)
__device__ float  g_t3  [(size_t)CN * DOUTD];   // GEMM3 out (fp32, gathered)
__device__ float  g_a3  [(size_t)CN * DOUTD];   // pooled input (fp32)
__device__ __half g_pool[(size_t)CG * DOUTD];   // head GEMM1 A (fp16)
__device__ __half g_mlp1[(size_t)CG * DOUTD];   // head GEMM2 A (fp16)
// fp16 k-pair-packed weights: Wp[k2*N + n] = half2(W[2k2][n], W[2k2+1][n])
__device__ uint32_t g_wp1 [(DIN / 2) * DH];
__device__ uint32_t g_wp2 [(DH / 2) * DH];
__device__ uint32_t g_wp3 [(DH / 2) * DOUTD];
__device__ uint32_t g_wpf1[(DOUTD / 2) * DOUTD];
__device__ uint32_t g_wpf2[(DOUTD / 2) * DOUTD];

// ---------------- small utility kernels --------------------------------------
__global__ void k_zero_i(int* __restrict__ p, int n) {
    unsigned i = blockIdx.x * blockDim.x + threadIdx.x;
    if (i < (unsigned)n) p[i] = 0;
}

__global__ void k_hist(const int* __restrict__ keys, int n, int* __restrict__ cnt) {
    unsigned i = blockIdx.x * blockDim.x + threadIdx.x;
    if (i < (unsigned)n) atomicAdd(&cnt[keys[i]], 1);
}

__global__ void k_dinv_from_cnt(const int* __restrict__ cnt, float* __restrict__ dinv) {
    unsigned i = blockIdx.x * blockDim.x + threadIdx.x;
    if (i < CN) dinv[i] = rsqrtf((float)(cnt[i] + 1));
}

__global__ void k_scan_block(const int* __restrict__ in, int* __restrict__ out,
                             int* __restrict__ bsum, int n) {
    __shared__ int sh[256];
    int t = threadIdx.x;
    int i = blockIdx.x * 256 + t;
    int v = (i < n) ? in[i] : 0;
    sh[t] = v; __syncthreads();
#pragma unroll
    for (int o = 1; o < 256; o <<= 1) {
        int x = (t >= o) ? sh[t - o] : 0;
        __syncthreads();
        sh[t] += x;
        __syncthreads();
    }
    if (i < n) out[i] = sh[t] - v;
    if (t == 255) bsum[blockIdx.x] = sh[255];
}

__global__ void k_scan_partials(int* __restrict__ bsum, int nb) {
    __shared__ int sh[1024];
    int t = threadIdx.x;
    int v = (t < nb) ? bsum[t] : 0;
    sh[t] = v; __syncthreads();
#pragma unroll
    for (int o = 1; o < 1024; o <<= 1) {
        int x = (t >= o) ? sh[t - o] : 0;
        __syncthreads();
        sh[t] += x;
        __syncthreads();
    }
    if (t < nb) bsum[t] = sh[t] - v;
}

__global__ void k_scan_add(int* __restrict__ out, const int* __restrict__ bsum,
                           int n, int total) {
    unsigned i = blockIdx.x * blockDim.x + threadIdx.x;
    if (i < (unsigned)n) out[i] += bsum[i >> 8];
    if (i == 0) out[n] = total;
}

__global__ void k_csr_scatter(const int* __restrict__ src, const int* __restrict__ dst,
                              const float* __restrict__ dinv,
                              const int* __restrict__ noff, int* __restrict__ cur,
                              int* __restrict__ csrc, float* __restrict__ cw) {
    unsigned e = blockIdx.x * blockDim.x + threadIdx.x;
    if (e >= CE) return;
    int d = dst[e], s = src[e];
    int pos = noff[d] + atomicAdd(&cur[d], 1);
    csrc[pos] = s;
    cw[pos] = dinv[s] * dinv[d];
}

__global__ void k_bnprep(const float* __restrict__ g, const float* __restrict__ be,
                         const float* __restrict__ m, const float* __restrict__ v,
                         float* __restrict__ s, float* __restrict__ sh, int n) {
    unsigned i = blockIdx.x * blockDim.x + threadIdx.x;
    if (i >= (unsigned)n) return;
    float sc = g[i] * rsqrtf(v[i] + BN_EPS);
    s[i] = sc;
    sh[i] = be[i] - m[i] * sc;
}

// pack W[K,N] fp32 -> Wp[K/2, N] uint32 (half2 over adjacent k)
__global__ void k_wpack(const float* __restrict__ W, uint32_t* __restrict__ Wp,
                        int K, int N) {
    unsigned i = blockIdx.x * blockDim.x + threadIdx.x;
    if (i >= (unsigned)((K / 2) * N)) return;
    int k2 = i / N, n = i % N;
    __half2 h = __floats2half2_rn(W[(size_t)(2 * k2) * N + n],
                                  W[(size_t)(2 * k2 + 1) * N + n]);
    Wp[i] = *reinterpret_cast<uint32_t*>(&h);
}

// ---------------- CSR aggregation (gather, 4-way MLP pipeline) ----------------
// OH: write output as fp16 (half2 pairs); else fp32 float4
template <int D, bool BN, bool OH>
__global__ __launch_bounds__(128) void k_agg_csr(
    const float* __restrict__ t, void* __restrict__ out,
    const int* __restrict__ noff, const int* __restrict__ csrc,
    const float* __restrict__ cw, const float* __restrict__ dinv,
    const float* __restrict__ bias, const float* __restrict__ bns,
    const float* __restrict__ bnsh) {
    constexpr int TPN = D / 4;
    constexpr int NPB = 128 / TPN;
    int node = blockIdx.x * NPB + threadIdx.x / TPN;
    int lane = threadIdx.x % TPN;
    int c = lane * 4;

    float di = dinv[node];
    float4 acc = *reinterpret_cast<const float4*>(t + (size_t)node * D + c);
    float w0n = di * di;
    acc.x *= w0n; acc.y *= w0n; acc.z *= w0n; acc.w *= w0n;

    int beg = noff[node], end = noff[node + 1];
    int p = beg;
    // 4-way unrolled: 4 independent index loads, then 4 independent row gathers
    for (; p + 3 < end; p += 4) {
        int s0 = csrc[p], s1 = csrc[p + 1], s2 = csrc[p + 2], s3 = csrc[p + 3];
        float w0 = cw[p], w1 = cw[p + 1], w2 = cw[p + 2], w3 = cw[p + 3];
        float4 v0 = *reinterpret_cast<const float4*>(t + (size_t)s0 * D + c);
        float4 v1 = *reinterpret_cast<const float4*>(t + (size_t)s1 * D + c);
        float4 v2 = *reinterpret_cast<const float4*>(t + (size_t)s2 * D + c);
        float4 v3 = *reinterpret_cast<const float4*>(t + (size_t)s3 * D + c);
        acc.x += v0.x * w0; acc.y += v0.y * w0; acc.z += v0.z * w0; acc.w += v0.w * w0;
        acc.x += v1.x * w1; acc.y += v1.y * w1; acc.z += v1.z * w1; acc.w += v1.w * w1;
        acc.x += v2.x * w2; acc.y += v2.y * w2; acc.z += v2.z * w2; acc.w += v2.w * w2;
        acc.x += v3.x * w3; acc.y += v3.y * w3; acc.z += v3.z * w3; acc.w += v3.w * w3;
    }
    if (p + 1 < end) {   // 2-way remainder
        int s0 = csrc[p], s1 = csrc[p + 1];
        float w0 = cw[p], w1 = cw[p + 1];
        float4 v0 = *reinterpret_cast<const float4*>(t + (size_t)s0 * D + c);
        float4 v1 = *reinterpret_cast<const float4*>(t + (size_t)s1 * D + c);
        acc.x += v0.x * w0; acc.y += v0.y * w0; acc.z += v0.z * w0; acc.w += v0.w * w0;
        acc.x += v1.x * w1; acc.y += v1.y * w1; acc.z += v1.z * w1; acc.w += v1.w * w1;
        p += 2;
    }
    if (p < end) {
        int s0 = csrc[p];
        float w0 = cw[p];
        float4 v0 = *reinterpret_cast<const float4*>(t + (size_t)s0 * D + c);
        acc.x += v0.x * w0; acc.y += v0.y * w0; acc.z += v0.z * w0; acc.w += v0.w * w0;
    }

    if (BN) {
        float4 b = *reinterpret_cast<const float4*>(bias + c);
        float4 s4 = *reinterpret_cast<const float4*>(bns + c);
        float4 h4 = *reinterpret_cast<const float4*>(bnsh + c);
        acc.x = fmaxf(acc.x + b.x, 0.0f) * s4.x + h4.x;
        acc.y = fmaxf(acc.y + b.y, 0.0f) * s4.y + h4.y;
        acc.z = fmaxf(acc.z + b.z, 0.0f) * s4.z + h4.z;
        acc.w = fmaxf(acc.w + b.w, 0.0f) * s4.w + h4.w;
    }
    if (OH) {
        __half2* op = reinterpret_cast<__half2*>((__half*)out + (size_t)node * D + c);
        op[0] = __floats2half2_rn(acc.x, acc.y);
        op[1] = __floats2half2_rn(acc.z, acc.w);
    } else {
        *reinterpret_cast<float4*>((float*)out + (size_t)node * D + c) = acc;
    }
}

// ---------------- segment mean pool (fp32 in, fp16 out) -----------------------
__global__ __launch_bounds__(128) void k_pool_seg(const float* __restrict__ h,
                                                  const int* __restrict__ goff,
                                                  __half* __restrict__ pooled) {
    int g = blockIdx.x * 2 + threadIdx.x / 64;
    int lane = threadIdx.x % 64;
    int c = lane * 4;
    int beg = goff[g], end = goff[g + 1];
    float4 acc = make_float4(0.f, 0.f, 0.f, 0.f);
    for (int n = beg; n < end; n++) {
        float4 v = *reinterpret_cast<const float4*>(h + (size_t)n * DOUTD + c);
        acc.x += v.x; acc.y += v.y; acc.z += v.z; acc.w += v.w;
    }
    float inv = 1.0f / fmaxf((float)(end - beg), 1.0f);
    __half2* op = reinterpret_cast<__half2*>(pooled + (size_t)g * DOUTD + c);
    op[0] = __floats2half2_rn(acc.x * inv, acc.y * inv);
    op[1] = __floats2half2_rn(acc.z * inv, acc.w * inv);
}

// ---------------- FP16 tensor-core GEMM (double-buffered) ---------------------
__device__ __forceinline__ void mma_f16(float* c, const uint32_t* a, const uint32_t* b) {
    asm volatile(
        "mma.sync.aligned.m16n8k16.row.col.f32.f16.f16.f32 "
        "{%0,%1,%2,%3}, {%4,%5,%6,%7}, {%8,%9}, {%0,%1,%2,%3};"
        : "+f"(c[0]), "+f"(c[1]), "+f"(c[2]), "+f"(c[3])
        : "r"(a[0]), "r"(a[1]), "r"(a[2]), "r"(a[3]), "r"(b[0]), "r"(b[1]));
}

#define GSTRIDE 136

// EPI: 0=none, 1=bias+relu+BN, 2=bias+relu, 3=bias ; OH: fp16 output
template <int EPI, bool OH>
__global__ __launch_bounds__(256, 2) void k_hgemm(
    const __half* __restrict__ A, const uint32_t* __restrict__ Wp, void* __restrict__ C,
    int M, int K, int Nn,
    const float* __restrict__ bias, const float* __restrict__ bns,
    const float* __restrict__ bnsh) {
    __shared__ uint32_t As[2][16][GSTRIDE];   // [buf][k2][m]
    __shared__ uint32_t Bs[2][16][GSTRIDE];   // [buf][k2][n]

    const int tid = threadIdx.x;
    const int bc = blockIdx.x, br = blockIdx.y;
    const int lane = tid & 31;
    const int wid = tid >> 5;
    const int wm = (wid >> 2) * 64;
    const int wn = (wid & 3) * 32;

    const int arow = tid >> 1;
    const int ak2 = (tid & 1) * 8;
    const int bn4 = (tid & 31) * 4;
    const int brow = tid >> 5;

    const int K2 = K >> 1;
    const uint32_t* Aptr = reinterpret_cast<const uint32_t*>(A)
                           + (size_t)(br * 128 + arow) * K2 + ak2;
    const uint32_t* Bptr = Wp + (size_t)brow * Nn + bc * 128 + bn4;
    const size_t BchunkStep = (size_t)16 * Nn;

    float acc[4][4][4];
#pragma unroll
    for (int mf = 0; mf < 4; mf++)
#pragma unroll
        for (int nf = 0; nf < 4; nf++)
#pragma unroll
            for (int r = 0; r < 4; r++) acc[mf][nf][r] = 0.0f;

    const int nchunks = K >> 5;

    uint4 ra0, ra1, rb0, rb1;
    ra0 = *reinterpret_cast<const uint4*>(Aptr);
    ra1 = *reinterpret_cast<const uint4*>(Aptr + 4);
    rb0 = *reinterpret_cast<const uint4*>(Bptr);
    rb1 = *reinterpret_cast<const uint4*>(Bptr + 8 * Nn);
    {
        As[0][ak2 + 0][arow] = ra0.x; As[0][ak2 + 1][arow] = ra0.y;
        As[0][ak2 + 2][arow] = ra0.z; As[0][ak2 + 3][arow] = ra0.w;
        As[0][ak2 + 4][arow] = ra1.x; As[0][ak2 + 5][arow] = ra1.y;
        As[0][ak2 + 6][arow] = ra1.z; As[0][ak2 + 7][arow] = ra1.w;
        *reinterpret_cast<uint4*>(&Bs[0][brow][bn4]) = rb0;
        *reinterpret_cast<uint4*>(&Bs[0][brow + 8][bn4]) = rb1;
    }
    __syncthreads();

    const int gr = lane >> 2;
    const int gc = lane & 3;

    for (int i = 0; i < nchunks; i++) {
        if (i + 1 < nchunks) {
            const uint32_t* Ap = Aptr + (i + 1) * 16;
            const uint32_t* Bp = Bptr + (size_t)(i + 1) * BchunkStep;
            ra0 = *reinterpret_cast<const uint4*>(Ap);
            ra1 = *reinterpret_cast<const uint4*>(Ap + 4);
            rb0 = *reinterpret_cast<const uint4*>(Bp);
            rb1 = *reinterpret_cast<const uint4*>(Bp + 8 * Nn);
        }

        const int cb = i & 1;
#pragma unroll
        for (int ks2 = 0; ks2 < 16; ks2 += 8) {
            uint32_t af[4][4];
#pragma unroll
            for (int mf = 0; mf < 4; mf++) {
                int mb = wm + mf * 16;
                af[mf][0] = As[cb][ks2 + gc][mb + gr];
                af[mf][1] = As[cb][ks2 + gc][mb + gr + 8];
                af[mf][2] = As[cb][ks2 + gc + 4][mb + gr];
                af[mf][3] = As[cb][ks2 + gc + 4][mb + gr + 8];
            }
            uint32_t bf[4][2];
#pragma unroll
            for (int nf = 0; nf < 4; nf++) {
                int nb = wn + nf * 8;
                bf[nf][0] = Bs[cb][ks2 + gc][nb + gr];
                bf[nf][1] = Bs[cb][ks2 + gc + 4][nb + gr];
            }
#pragma unroll
            for (int mf = 0; mf < 4; mf++)
#pragma unroll
                for (int nf = 0; nf < 4; nf++)
                    mma_f16(acc[mf][nf], af[mf], bf[nf]);
        }

        if (i + 1 < nchunks) {
            const int nb2 = (i + 1) & 1;
            As[nb2][ak2 + 0][arow] = ra0.x; As[nb2][ak2 + 1][arow] = ra0.y;
            As[nb2][ak2 + 2][arow] = ra0.z; As[nb2][ak2 + 3][arow] = ra0.w;
            As[nb2][ak2 + 4][arow] = ra1.x; As[nb2][ak2 + 5][arow] = ra1.y;
            As[nb2][ak2 + 6][arow] = ra1.z; As[nb2][ak2 + 7][arow] = ra1.w;
            *reinterpret_cast<uint4*>(&Bs[nb2][brow][bn4]) = rb0;
            *reinterpret_cast<uint4*>(&Bs[nb2][brow + 8][bn4]) = rb1;
        }
        __syncthreads();
    }

    float* Cf = reinterpret_cast<float*>(C);
    __half* Ch = reinterpret_cast<__half*>(C);
#pragma unroll
    for (int nf = 0; nf < 4; nf++) {
        int col = bc * 128 + wn + nf * 8 + gc * 2;
        float bb0 = 0.f, bb1 = 0.f, s0 = 1.f, s1 = 1.f, h0 = 0.f, h1 = 0.f;
        if (EPI != 0) { bb0 = bias[col]; bb1 = bias[col + 1]; }
        if (EPI == 1) {
            s0 = bns[col]; s1 = bns[col + 1];
            h0 = bnsh[col]; h1 = bnsh[col + 1];
        }
#pragma unroll
        for (int mf = 0; mf < 4; mf++) {
            int row0 = br * 128 + wm + mf * 16 + gr;
            float v0 = acc[mf][nf][0], v1 = acc[mf][nf][1];
            float v2 = acc[mf][nf][2], v3 = acc[mf][nf][3];
            if (EPI != 0) { v0 += bb0; v1 += bb1; v2 += bb0; v3 += bb1; }
            if (EPI == 1 || EPI == 2) {
                v0 = fmaxf(v0, 0.f); v1 = fmaxf(v1, 0.f);
                v2 = fmaxf(v2, 0.f); v3 = fmaxf(v3, 0.f);
            }
            if (EPI == 1) {
                v0 = v0 * s0 + h0; v1 = v1 * s1 + h1;
                v2 = v2 * s0 + h0; v3 = v3 * s1 + h1;
            }
            if (OH) {
                *reinterpret_cast<__half2*>(Ch + (size_t)row0 * Nn + col) =
                    __floats2half2_rn(v0, v1);
                *reinterpret_cast<__half2*>(Ch + (size_t)(row0 + 8) * Nn + col) =
                    __floats2half2_rn(v2, v3);
            } else {
                *reinterpret_cast<float2*>(Cf + (size_t)row0 * Nn + col) = make_float2(v0, v1);
                *reinterpret_cast<float2*>(Cf + (size_t)(row0 + 8) * Nn + col) = make_float2(v2, v3);
            }
        }
    }
}

// ---------------- launch -----------------------------------------------------
extern "C" void kernel_launch(void* const* d_in, const int* in_sizes, int n_in,
                              void* d_out, int out_size) {
    const float* x   = (const float*)d_in[0];
    const int* ei    = (const int*)d_in[1];
    const int* batch = (const int*)d_in[2];
    const float* W1  = (const float*)d_in[3];  const float* b1  = (const float*)d_in[4];
    const float* W2  = (const float*)d_in[5];  const float* b2  = (const float*)d_in[6];
    const float* W3  = (const float*)d_in[7];  const float* b3  = (const float*)d_in[8];
    const float* g1  = (const float*)d_in[9];  const float* be1 = (const float*)d_in[10];
    const float* m1  = (const float*)d_in[11]; const float* v1  = (const float*)d_in[12];
    const float* g2  = (const float*)d_in[13]; const float* be2 = (const float*)d_in[14];
    const float* m2  = (const float*)d_in[15]; const float* v2  = (const float*)d_in[16];
    const float* g3  = (const float*)d_in[17]; const float* be3 = (const float*)d_in[18];
    const float* m3  = (const float*)d_in[19]; const float* v3  = (const float*)d_in[20];
    const float* Wf1 = (const float*)d_in[21]; const float* bf1 = (const float*)d_in[22];
    const float* Wf2 = (const float*)d_in[23]; const float* bf2 = (const float*)d_in[24];
    float* out = (float*)d_out;

    const int* src = ei;
    const int* dst = ei + CE;

    float *dinv, *cw, *t2, *t3, *a3, *bns, *bnsh;
    __half *agg1, *h1, *a2, *pool, *mlp1;
    uint32_t *wp1, *wp2, *wp3, *wpf1, *wpf2;
    int *cnt, *noff, *cur, *bsum, *csrc, *gcnt, *goff, *gbsum;
    cudaGetSymbolAddress((void**)&dinv, g_dinv);
    cudaGetSymbolAddress((void**)&cnt,  g_cnt);
    cudaGetSymbolAddress((void**)&noff, g_noff);
    cudaGetSymbolAddress((void**)&cur,  g_cur);
    cudaGetSymbolAddress((void**)&bsum, g_bsum);
    cudaGetSymbolAddress((void**)&csrc, g_csrc);
    cudaGetSymbolAddress((void**)&cw,   g_cw);
    cudaGetSymbolAddress((void**)&gcnt, g_gcnt);
    cudaGetSymbolAddress((void**)&goff, g_goff);
    cudaGetSymbolAddress((void**)&gbsum, g_gbsum);
    cudaGetSymbolAddress((void**)&bns,  g_bns);
    cudaGetSymbolAddress((void**)&bnsh, g_bnsh);
    cudaGetSymbolAddress((void**)&agg1, g_agg1);
    cudaGetSymbolAddress((void**)&h1,   g_h1);
    cudaGetSymbolAddress((void**)&t2,   g_t2);
    cudaGetSymbolAddress((void**)&a2,   g_a2);
    cudaGetSymbolAddress((void**)&t3,   g_t3);
    cudaGetSymbolAddress((void**)&a3,   g_a3);
    cudaGetSymbolAddress((void**)&pool, g_pool);
    cudaGetSymbolAddress((void**)&mlp1, g_mlp1);
    cudaGetSymbolAddress((void**)&wp1,  g_wp1);
    cudaGetSymbolAddress((void**)&wp2,  g_wp2);
    cudaGetSymbolAddress((void**)&wp3,  g_wp3);
    cudaGetSymbolAddress((void**)&wpf1, g_wpf1);
    cudaGetSymbolAddress((void**)&wpf2, g_wpf2);

    const int T = 256;

    // ---- pack weights to fp16 ----
    k_wpack<<<((DIN / 2) * DH + T - 1) / T, T>>>(W1, wp1, DIN, DH);
    k_wpack<<<((DH / 2) * DH + T - 1) / T, T>>>(W2, wp2, DH, DH);
    k_wpack<<<((DH / 2) * DOUTD + T - 1) / T, T>>>(W3, wp3, DH, DOUTD);
    k_wpack<<<((DOUTD / 2) * DOUTD + T - 1) / T, T>>>(Wf1, wpf1, DOUTD, DOUTD);
    k_wpack<<<((DOUTD / 2) * DOUTD + T - 1) / T, T>>>(Wf2, wpf2, DOUTD, DOUTD);

    // ---- CSR build ----
    k_zero_i<<<(CN + T - 1) / T, T>>>(cnt, CN);
    k_zero_i<<<(CN + T - 1) / T, T>>>(cur, CN);
    k_zero_i<<<(CG + T - 1) / T, T>>>(gcnt, CG);
    k_hist<<<(CE + T - 1) / T, T>>>(dst, CE, cnt);
    k_hist<<<(CN + T - 1) / T, T>>>(batch, CN, gcnt);
    k_dinv_from_cnt<<<(CN + T - 1) / T, T>>>(cnt, dinv);
    k_scan_block<<<CN / 256, 256>>>(cnt, noff, bsum, CN);
    k_scan_partials<<<1, 1024>>>(bsum, CN / 256);
    k_scan_add<<<(CN + T - 1) / T, T>>>(noff, bsum, CN, CE);
    k_scan_block<<<CG / 256, 256>>>(gcnt, goff, gbsum, CG);
    k_scan_partials<<<1, 1024>>>(gbsum, CG / 256);
    k_scan_add<<<(CG + T - 1) / T, T>>>(goff, gbsum, CG, CN);
    k_csr_scatter<<<(CE + T - 1) / T, T>>>(src, dst, dinv, noff, cur, csrc, cw);

    // ---- layer1 BN consts ----
    k_bnprep<<<(DH + T - 1) / T, T>>>(g1, be1, m1, v1, bns, bnsh, DH);

    // ---- layer 1: aggregate (fp32 in, fp16 out) then GEMM (bias+relu+BN) ----
    k_agg_csr<DIN, false, true><<<CN / 4, 128>>>(x, agg1, noff, csrc, cw, dinv,
                                                 nullptr, nullptr, nullptr);
    {
        dim3 grid(DH / 128, CN / 128);
        k_hgemm<1, true><<<grid, 256>>>(agg1, wp1, h1, CN, DIN, DH, b1, bns, bnsh);
    }

    // re-prep BN consts for layers 2 & 3
    k_bnprep<<<(DH + T - 1) / T, T>>>(g2, be2, m2, v2, bns, bnsh, DH);
    k_bnprep<<<(DOUTD + T - 1) / T, T>>>(g3, be3, m3, v3, bns + DH, bnsh + DH, DOUTD);

    // ---- layer 2: GEMM (fp32 out) then aggregate (fp16 out) ----
    {
        dim3 grid(DH / 128, CN / 128);
        k_hgemm<0, false><<<grid, 256>>>(h1, wp2, t2, CN, DH, DH, nullptr, nullptr, nullptr);
    }
    k_agg_csr<DH, true, true><<<CN, 128>>>(t2, a2, noff, csrc, cw, dinv, b2, bns, bnsh);

    // ---- layer 3: GEMM (fp32 out) then aggregate (fp32 out) ----
    {
        dim3 grid(DOUTD / 128, CN / 128);
        k_hgemm<0, false><<<grid, 256>>>(a2, wp3, t3, CN, DH, DOUTD, nullptr, nullptr, nullptr);
    }
    k_agg_csr<DOUTD, true, false><<<CN / 2, 128>>>(t3, a3, noff, csrc, cw, dinv,
                                                   b3, bns + DH, bnsh + DH);

    // ---- segment mean pool (fp16 out) ----
    k_pool_seg<<<CG / 2, 128>>>(a3, goff, pool);

    // ---- MLP head ----
    {
        dim3 grid(DOUTD / 128, CG / 128);
        k_hgemm<2, true><<<grid, 256>>>(pool, wpf1, mlp1, CG, DOUTD, DOUTD, bf1, nullptr, nullptr);
        k_hgemm<3, false><<<grid, 256>>>(mlp1, wpf2, out, CG, DOUTD, DOUTD, bf2, nullptr, nullptr);
    }
}

// round 11
// speedup vs baseline: 1.1513x; 1.0967x over previous
#include <cuda_runtime.h>
#include <cuda_fp16.h>
#include <math.h>
#include <stdint.h>

#define CN 131072
#define CE 524288
#define CG 4096
#define DIN 128
#define DH  512
#define DOUTD 256
#define BN_EPS 1e-5f

// ---------------- scratch (static device globals; no allocation) -------------
__device__ float g_dinv[CN];
__device__ int   g_cnt [CN];
__device__ int   g_noff[CN + 1];
__device__ int   g_cur [CN];
__device__ int   g_bsum[512];
__device__ int   g_csrc[CE];
__device__ float g_cw  [CE];
__device__ int   g_gcnt[CG];
__device__ int   g_goff[CG + 1];
__device__ int   g_gbsum[16];
__device__ float g_bns [DH + DOUTD];
__device__ float g_bnsh[DH + DOUTD];
__device__ __half g_agg1[(size_t)CN * DIN];     // GEMM1 A (fp16)
__device__ __half g_h1  [(size_t)CN * DH];      // GEMM1 out = layer2 agg input (fp16)
__device__ __half g_ah1 [(size_t)CN * DH];      // agg(h1) = GEMM2 A (fp16)
__device__ __half g_a2  [(size_t)CN * DH];      // GEMM2 out (fused BN) = GEMM3 A (fp16)
__device__ __half g_t3  [(size_t)CN * DOUTD];   // GEMM3 out (fp16, gathered)
__device__ float  g_a3  [(size_t)CN * DOUTD];   // layer3 out (fp32) -> pool
__device__ __half g_pool[(size_t)CG * DOUTD];   // head GEMM1 A (fp16)
__device__ __half g_mlp1[(size_t)CG * DOUTD];   // head GEMM2 A (fp16)
// fp16 k-pair-packed weights: Wp[k2*N + n] = half2(W[2k2][n], W[2k2+1][n])
__device__ uint32_t g_wp1 [(DIN / 2) * DH];
__device__ uint32_t g_wp2 [(DH / 2) * DH];
__device__ uint32_t g_wp3 [(DH / 2) * DOUTD];
__device__ uint32_t g_wpf1[(DOUTD / 2) * DOUTD];
__device__ uint32_t g_wpf2[(DOUTD / 2) * DOUTD];

// ---------------- small utility kernels --------------------------------------
__global__ void k_zero_i(int* __restrict__ p, int n) {
    unsigned i = blockIdx.x * blockDim.x + threadIdx.x;
    if (i < (unsigned)n) p[i] = 0;
}

__global__ void k_hist(const int* __restrict__ keys, int n, int* __restrict__ cnt) {
    unsigned i = blockIdx.x * blockDim.x + threadIdx.x;
    if (i < (unsigned)n) atomicAdd(&cnt[keys[i]], 1);
}

__global__ void k_dinv_from_cnt(const int* __restrict__ cnt, float* __restrict__ dinv) {
    unsigned i = blockIdx.x * blockDim.x + threadIdx.x;
    if (i < CN) dinv[i] = rsqrtf((float)(cnt[i] + 1));
}

__global__ void k_scan_block(const int* __restrict__ in, int* __restrict__ out,
                             int* __restrict__ bsum, int n) {
    __shared__ int sh[256];
    int t = threadIdx.x;
    int i = blockIdx.x * 256 + t;
    int v = (i < n) ? in[i] : 0;
    sh[t] = v; __syncthreads();
#pragma unroll
    for (int o = 1; o < 256; o <<= 1) {
        int x = (t >= o) ? sh[t - o] : 0;
        __syncthreads();
        sh[t] += x;
        __syncthreads();
    }
    if (i < n) out[i] = sh[t] - v;
    if (t == 255) bsum[blockIdx.x] = sh[255];
}

__global__ void k_scan_partials(int* __restrict__ bsum, int nb) {
    __shared__ int sh[1024];
    int t = threadIdx.x;
    int v = (t < nb) ? bsum[t] : 0;
    sh[t] = v; __syncthreads();
#pragma unroll
    for (int o = 1; o < 1024; o <<= 1) {
        int x = (t >= o) ? sh[t - o] : 0;
        __syncthreads();
        sh[t] += x;
        __syncthreads();
    }
    if (t < nb) bsum[t] = sh[t] - v;
}

__global__ void k_scan_add(int* __restrict__ out, const int* __restrict__ bsum,
                           int n, int total) {
    unsigned i = blockIdx.x * blockDim.x + threadIdx.x;
    if (i < (unsigned)n) out[i] += bsum[i >> 8];
    if (i == 0) out[n] = total;
}

__global__ void k_csr_scatter(const int* __restrict__ src, const int* __restrict__ dst,
                              const float* __restrict__ dinv,
                              const int* __restrict__ noff, int* __restrict__ cur,
                              int* __restrict__ csrc, float* __restrict__ cw) {
    unsigned e = blockIdx.x * blockDim.x + threadIdx.x;
    if (e >= CE) return;
    int d = dst[e], s = src[e];
    int pos = noff[d] + atomicAdd(&cur[d], 1);
    csrc[pos] = s;
    cw[pos] = dinv[s] * dinv[d];
}

__global__ void k_bnprep(const float* __restrict__ g, const float* __restrict__ be,
                         const float* __restrict__ m, const float* __restrict__ v,
                         float* __restrict__ s, float* __restrict__ sh, int n) {
    unsigned i = blockIdx.x * blockDim.x + threadIdx.x;
    if (i >= (unsigned)n) return;
    float sc = g[i] * rsqrtf(v[i] + BN_EPS);
    s[i] = sc;
    sh[i] = be[i] - m[i] * sc;
}

// pack W[K,N] fp32 -> Wp[K/2, N] uint32 (half2 over adjacent k)
__global__ void k_wpack(const float* __restrict__ W, uint32_t* __restrict__ Wp,
                        int K, int N) {
    unsigned i = blockIdx.x * blockDim.x + threadIdx.x;
    if (i >= (unsigned)((K / 2) * N)) return;
    int k2 = i / N, n = i % N;
    __half2 h = __floats2half2_rn(W[(size_t)(2 * k2) * N + n],
                                  W[(size_t)(2 * k2 + 1) * N + n]);
    Wp[i] = *reinterpret_cast<uint32_t*>(&h);
}

// ---------------- CSR aggregation: fp32 input (layer 1), fp16 output ---------
__global__ __launch_bounds__(128) void k_agg_csr_f(
    const float* __restrict__ t, __half* __restrict__ out,
    const int* __restrict__ noff, const int* __restrict__ csrc,
    const float* __restrict__ cw, const float* __restrict__ dinv) {
    constexpr int D = DIN;
    constexpr int TPN = D / 4;        // 32
    constexpr int NPB = 128 / TPN;    // 4
    int node = blockIdx.x * NPB + threadIdx.x / TPN;
    int lane = threadIdx.x % TPN;
    int c = lane * 4;

    float di = dinv[node];
    float4 acc = *reinterpret_cast<const float4*>(t + (size_t)node * D + c);
    float w0 = di * di;
    acc.x *= w0; acc.y *= w0; acc.z *= w0; acc.w *= w0;

    int beg = noff[node], end = noff[node + 1];
    for (int p = beg; p < end; p++) {
        int s = csrc[p];
        float w = cw[p];
        float4 v = *reinterpret_cast<const float4*>(t + (size_t)s * D + c);
        acc.x += v.x * w; acc.y += v.y * w; acc.z += v.z * w; acc.w += v.w * w;
    }
    __half2* op = reinterpret_cast<__half2*>(out + (size_t)node * D + c);
    op[0] = __floats2half2_rn(acc.x, acc.y);
    op[1] = __floats2half2_rn(acc.z, acc.w);
}

// ---------------- CSR aggregation: fp16 input, same TLP as fp32 version -------
// TPN = D/4 threads per node (each handles 4 halves = one uint2 load per row).
// BN: fused bias+relu+BN; OH: fp16 output (else fp32).
template <int D, bool BN, bool OH>
__global__ __launch_bounds__(128) void k_agg_csr_h(
    const __half* __restrict__ t, void* __restrict__ out,
    const int* __restrict__ noff, const int* __restrict__ csrc,
    const float* __restrict__ cw, const float* __restrict__ dinv,
    const float* __restrict__ bias, const float* __restrict__ bns,
    const float* __restrict__ bnsh) {
    constexpr int TPN = D / 4;
    constexpr int NPB = 128 / TPN;
    int node = blockIdx.x * NPB + threadIdx.x / TPN;
    int lane = threadIdx.x % TPN;
    int c = lane * 4;

    float di = dinv[node];
    float w0 = di * di;
    float a0, a1, a2v, a3v;
    {
        uint2 raw = *reinterpret_cast<const uint2*>(t + (size_t)node * D + c);
        float2 f0 = __half22float2(*reinterpret_cast<__half2*>(&raw.x));
        float2 f1 = __half22float2(*reinterpret_cast<__half2*>(&raw.y));
        a0 = f0.x * w0; a1 = f0.y * w0; a2v = f1.x * w0; a3v = f1.y * w0;
    }

    int beg = noff[node], end = noff[node + 1];
    for (int p = beg; p < end; p++) {
        int s = csrc[p];
        float w = cw[p];
        uint2 raw = *reinterpret_cast<const uint2*>(t + (size_t)s * D + c);
        float2 f0 = __half22float2(*reinterpret_cast<__half2*>(&raw.x));
        float2 f1 = __half22float2(*reinterpret_cast<__half2*>(&raw.y));
        a0 += f0.x * w; a1 += f0.y * w; a2v += f1.x * w; a3v += f1.y * w;
    }

    if (BN) {
        float4 b = *reinterpret_cast<const float4*>(bias + c);
        float4 s4 = *reinterpret_cast<const float4*>(bns + c);
        float4 h4 = *reinterpret_cast<const float4*>(bnsh + c);
        a0 = fmaxf(a0 + b.x, 0.0f) * s4.x + h4.x;
        a1 = fmaxf(a1 + b.y, 0.0f) * s4.y + h4.y;
        a2v = fmaxf(a2v + b.z, 0.0f) * s4.z + h4.z;
        a3v = fmaxf(a3v + b.w, 0.0f) * s4.w + h4.w;
    }
    if (OH) {
        uint2 o;
        __half2 h0 = __floats2half2_rn(a0, a1);
        __half2 h1 = __floats2half2_rn(a2v, a3v);
        o.x = *reinterpret_cast<uint32_t*>(&h0);
        o.y = *reinterpret_cast<uint32_t*>(&h1);
        *reinterpret_cast<uint2*>((__half*)out + (size_t)node * D + c) = o;
    } else {
        *reinterpret_cast<float4*>((float*)out + (size_t)node * D + c) =
            make_float4(a0, a1, a2v, a3v);
    }
}

// ---------------- segment mean pool (fp32 in, fp16 out) -----------------------
__global__ __launch_bounds__(128) void k_pool_seg(const float* __restrict__ h,
                                                  const int* __restrict__ goff,
                                                  __half* __restrict__ pooled) {
    int g = blockIdx.x * 2 + threadIdx.x / 64;
    int lane = threadIdx.x % 64;
    int c = lane * 4;
    int beg = goff[g], end = goff[g + 1];
    float4 acc = make_float4(0.f, 0.f, 0.f, 0.f);
    for (int n = beg; n < end; n++) {
        float4 v = *reinterpret_cast<const float4*>(h + (size_t)n * DOUTD + c);
        acc.x += v.x; acc.y += v.y; acc.z += v.z; acc.w += v.w;
    }
    float inv = 1.0f / fmaxf((float)(end - beg), 1.0f);
    __half2* op = reinterpret_cast<__half2*>(pooled + (size_t)g * DOUTD + c);
    op[0] = __floats2half2_rn(acc.x * inv, acc.y * inv);
    op[1] = __floats2half2_rn(acc.z * inv, acc.w * inv);
}

// ---------------- FP16 tensor-core GEMM (double-buffered) ---------------------
__device__ __forceinline__ void mma_f16(float* c, const uint32_t* a, const uint32_t* b) {
    asm volatile(
        "mma.sync.aligned.m16n8k16.row.col.f32.f16.f16.f32 "
        "{%0,%1,%2,%3}, {%4,%5,%6,%7}, {%8,%9}, {%0,%1,%2,%3};"
        : "+f"(c[0]), "+f"(c[1]), "+f"(c[2]), "+f"(c[3])
        : "r"(a[0]), "r"(a[1]), "r"(a[2]), "r"(a[3]), "r"(b[0]), "r"(b[1]));
}

#define GSTRIDE 136

// EPI: 0=none, 1=bias+relu+BN, 2=bias+relu, 3=bias ; OH: fp16 output
template <int EPI, bool OH>
__global__ __launch_bounds__(256, 2) void k_hgemm(
    const __half* __restrict__ A, const uint32_t* __restrict__ Wp, void* __restrict__ C,
    int M, int K, int Nn,
    const float* __restrict__ bias, const float* __restrict__ bns,
    const float* __restrict__ bnsh) {
    __shared__ uint32_t As[2][16][GSTRIDE];   // [buf][k2][m]
    __shared__ uint32_t Bs[2][16][GSTRIDE];   // [buf][k2][n]

    const int tid = threadIdx.x;
    const int bc = blockIdx.x, br = blockIdx.y;
    const int lane = tid & 31;
    const int wid = tid >> 5;
    const int wm = (wid >> 2) * 64;
    const int wn = (wid & 3) * 32;

    const int arow = tid >> 1;
    const int ak2 = (tid & 1) * 8;
    const int bn4 = (tid & 31) * 4;
    const int brow = tid >> 5;

    const int K2 = K >> 1;
    const uint32_t* Aptr = reinterpret_cast<const uint32_t*>(A)
                           + (size_t)(br * 128 + arow) * K2 + ak2;
    const uint32_t* Bptr = Wp + (size_t)brow * Nn + bc * 128 + bn4;
    const size_t BchunkStep = (size_t)16 * Nn;

    float acc[4][4][4];
#pragma unroll
    for (int mf = 0; mf < 4; mf++)
#pragma unroll
        for (int nf = 0; nf < 4; nf++)
#pragma unroll
            for (int r = 0; r < 4; r++) acc[mf][nf][r] = 0.0f;

    const int nchunks = K >> 5;

    uint4 ra0, ra1, rb0, rb1;
    ra0 = *reinterpret_cast<const uint4*>(Aptr);
    ra1 = *reinterpret_cast<const uint4*>(Aptr + 4);
    rb0 = *reinterpret_cast<const uint4*>(Bptr);
    rb1 = *reinterpret_cast<const uint4*>(Bptr + 8 * Nn);
    {
        As[0][ak2 + 0][arow] = ra0.x; As[0][ak2 + 1][arow] = ra0.y;
        As[0][ak2 + 2][arow] = ra0.z; As[0][ak2 + 3][arow] = ra0.w;
        As[0][ak2 + 4][arow] = ra1.x; As[0][ak2 + 5][arow] = ra1.y;
        As[0][ak2 + 6][arow] = ra1.z; As[0][ak2 + 7][arow] = ra1.w;
        *reinterpret_cast<uint4*>(&Bs[0][brow][bn4]) = rb0;
        *reinterpret_cast<uint4*>(&Bs[0][brow + 8][bn4]) = rb1;
    }
    __syncthreads();

    const int gr = lane >> 2;
    const int gc = lane & 3;

    for (int i = 0; i < nchunks; i++) {
        if (i + 1 < nchunks) {
            const uint32_t* Ap = Aptr + (i + 1) * 16;
            const uint32_t* Bp = Bptr + (size_t)(i + 1) * BchunkStep;
            ra0 = *reinterpret_cast<const uint4*>(Ap);
            ra1 = *reinterpret_cast<const uint4*>(Ap + 4);
            rb0 = *reinterpret_cast<const uint4*>(Bp);
            rb1 = *reinterpret_cast<const uint4*>(Bp + 8 * Nn);
        }

        const int cb = i & 1;
#pragma unroll
        for (int ks2 = 0; ks2 < 16; ks2 += 8) {
            uint32_t af[4][4];
#pragma unroll
            for (int mf = 0; mf < 4; mf++) {
                int mb = wm + mf * 16;
                af[mf][0] = As[cb][ks2 + gc][mb + gr];
                af[mf][1] = As[cb][ks2 + gc][mb + gr + 8];
                af[mf][2] = As[cb][ks2 + gc + 4][mb + gr];
                af[mf][3] = As[cb][ks2 + gc + 4][mb + gr + 8];
            }
            uint32_t bf[4][2];
#pragma unroll
            for (int nf = 0; nf < 4; nf++) {
                int nb = wn + nf * 8;
                bf[nf][0] = Bs[cb][ks2 + gc][nb + gr];
                bf[nf][1] = Bs[cb][ks2 + gc + 4][nb + gr];
            }
#pragma unroll
            for (int mf = 0; mf < 4; mf++)
#pragma unroll
                for (int nf = 0; nf < 4; nf++)
                    mma_f16(acc[mf][nf], af[mf], bf[nf]);
        }

        if (i + 1 < nchunks) {
            const int nb2 = (i + 1) & 1;
            As[nb2][ak2 + 0][arow] = ra0.x; As[nb2][ak2 + 1][arow] = ra0.y;
            As[nb2][ak2 + 2][arow] = ra0.z; As[nb2][ak2 + 3][arow] = ra0.w;
            As[nb2][ak2 + 4][arow] = ra1.x; As[nb2][ak2 + 5][arow] = ra1.y;
            As[nb2][ak2 + 6][arow] = ra1.z; As[nb2][ak2 + 7][arow] = ra1.w;
            *reinterpret_cast<uint4*>(&Bs[nb2][brow][bn4]) = rb0;
            *reinterpret_cast<uint4*>(&Bs[nb2][brow + 8][bn4]) = rb1;
        }
        __syncthreads();
    }

    float* Cf = reinterpret_cast<float*>(C);
    __half* Ch = reinterpret_cast<__half*>(C);
#pragma unroll
    for (int nf = 0; nf < 4; nf++) {
        int col = bc * 128 + wn + nf * 8 + gc * 2;
        float bb0 = 0.f, bb1 = 0.f, s0 = 1.f, s1 = 1.f, h0 = 0.f, h1 = 0.f;
        if (EPI != 0) { bb0 = bias[col]; bb1 = bias[col + 1]; }
        if (EPI == 1) {
            s0 = bns[col]; s1 = bns[col + 1];
            h0 = bnsh[col]; h1 = bnsh[col + 1];
        }
#pragma unroll
        for (int mf = 0; mf < 4; mf++) {
            int row0 = br * 128 + wm + mf * 16 + gr;
            float v0 = acc[mf][nf][0], v1 = acc[mf][nf][1];
            float v2 = acc[mf][nf][2], v3 = acc[mf][nf][3];
            if (EPI != 0) { v0 += bb0; v1 += bb1; v2 += bb0; v3 += bb1; }
            if (EPI == 1 || EPI == 2) {
                v0 = fmaxf(v0, 0.f); v1 = fmaxf(v1, 0.f);
                v2 = fmaxf(v2, 0.f); v3 = fmaxf(v3, 0.f);
            }
            if (EPI == 1) {
                v0 = v0 * s0 + h0; v1 = v1 * s1 + h1;
                v2 = v2 * s0 + h0; v3 = v3 * s1 + h1;
            }
            if (OH) {
                *reinterpret_cast<__half2*>(Ch + (size_t)row0 * Nn + col) =
                    __floats2half2_rn(v0, v1);
                *reinterpret_cast<__half2*>(Ch + (size_t)(row0 + 8) * Nn + col) =
                    __floats2half2_rn(v2, v3);
            } else {
                *reinterpret_cast<float2*>(Cf + (size_t)row0 * Nn + col) = make_float2(v0, v1);
                *reinterpret_cast<float2*>(Cf + (size_t)(row0 + 8) * Nn + col) = make_float2(v2, v3);
            }
        }
    }
}

// ---------------- launch -----------------------------------------------------
extern "C" void kernel_launch(void* const* d_in, const int* in_sizes, int n_in,
                              void* d_out, int out_size) {
    const float* x   = (const float*)d_in[0];
    const int* ei    = (const int*)d_in[1];
    const int* batch = (const int*)d_in[2];
    const float* W1  = (const float*)d_in[3];  const float* b1  = (const float*)d_in[4];
    const float* W2  = (const float*)d_in[5];  const float* b2  = (const float*)d_in[6];
    const float* W3  = (const float*)d_in[7];  const float* b3  = (const float*)d_in[8];
    const float* g1  = (const float*)d_in[9];  const float* be1 = (const float*)d_in[10];
    const float* m1  = (const float*)d_in[11]; const float* v1  = (const float*)d_in[12];
    const float* g2  = (const float*)d_in[13]; const float* be2 = (const float*)d_in[14];
    const float* m2  = (const float*)d_in[15]; const float* v2  = (const float*)d_in[16];
    const float* g3  = (const float*)d_in[17]; const float* be3 = (const float*)d_in[18];
    const float* m3  = (const float*)d_in[19]; const float* v3  = (const float*)d_in[20];
    const float* Wf1 = (const float*)d_in[21]; const float* bf1 = (const float*)d_in[22];
    const float* Wf2 = (const float*)d_in[23]; const float* bf2 = (const float*)d_in[24];
    float* out = (float*)d_out;

    const int* src = ei;
    const int* dst = ei + CE;

    float *dinv, *cw, *a3, *bns, *bnsh;
    __half *agg1, *h1, *ah1, *a2, *t3, *pool, *mlp1;
    uint32_t *wp1, *wp2, *wp3, *wpf1, *wpf2;
    int *cnt, *noff, *cur, *bsum, *csrc, *gcnt, *goff, *gbsum;
    cudaGetSymbolAddress((void**)&dinv, g_dinv);
    cudaGetSymbolAddress((void**)&cnt,  g_cnt);
    cudaGetSymbolAddress((void**)&noff, g_noff);
    cudaGetSymbolAddress((void**)&cur,  g_cur);
    cudaGetSymbolAddress((void**)&bsum, g_bsum);
    cudaGetSymbolAddress((void**)&csrc, g_csrc);
    cudaGetSymbolAddress((void**)&cw,   g_cw);
    cudaGetSymbolAddress((void**)&gcnt, g_gcnt);
    cudaGetSymbolAddress((void**)&goff, g_goff);
    cudaGetSymbolAddress((void**)&gbsum, g_gbsum);
    cudaGetSymbolAddress((void**)&bns,  g_bns);
    cudaGetSymbolAddress((void**)&bnsh, g_bnsh);
    cudaGetSymbolAddress((void**)&agg1, g_agg1);
    cudaGetSymbolAddress((void**)&h1,   g_h1);
    cudaGetSymbolAddress((void**)&ah1,  g_ah1);
    cudaGetSymbolAddress((void**)&a2,   g_a2);
    cudaGetSymbolAddress((void**)&t3,   g_t3);
    cudaGetSymbolAddress((void**)&a3,   g_a3);
    cudaGetSymbolAddress((void**)&pool, g_pool);
    cudaGetSymbolAddress((void**)&mlp1, g_mlp1);
    cudaGetSymbolAddress((void**)&wp1,  g_wp1);
    cudaGetSymbolAddress((void**)&wp2,  g_wp2);
    cudaGetSymbolAddress((void**)&wp3,  g_wp3);
    cudaGetSymbolAddress((void**)&wpf1, g_wpf1);
    cudaGetSymbolAddress((void**)&wpf2, g_wpf2);

    const int T = 256;

    // ---- pack weights to fp16 ----
    k_wpack<<<((DIN / 2) * DH + T - 1) / T, T>>>(W1, wp1, DIN, DH);
    k_wpack<<<((DH / 2) * DH + T - 1) / T, T>>>(W2, wp2, DH, DH);
    k_wpack<<<((DH / 2) * DOUTD + T - 1) / T, T>>>(W3, wp3, DH, DOUTD);
    k_wpack<<<((DOUTD / 2) * DOUTD + T - 1) / T, T>>>(Wf1, wpf1, DOUTD, DOUTD);
    k_wpack<<<((DOUTD / 2) * DOUTD + T - 1) / T, T>>>(Wf2, wpf2, DOUTD, DOUTD);

    // ---- CSR build ----
    k_zero_i<<<(CN + T - 1) / T, T>>>(cnt, CN);
    k_zero_i<<<(CN + T - 1) / T, T>>>(cur, CN);
    k_zero_i<<<(CG + T - 1) / T, T>>>(gcnt, CG);
    k_hist<<<(CE + T - 1) / T, T>>>(dst, CE, cnt);
    k_hist<<<(CN + T - 1) / T, T>>>(batch, CN, gcnt);
    k_dinv_from_cnt<<<(CN + T - 1) / T, T>>>(cnt, dinv);
    k_scan_block<<<CN / 256, 256>>>(cnt, noff, bsum, CN);
    k_scan_partials<<<1, 1024>>>(bsum, CN / 256);
    k_scan_add<<<(CN + T - 1) / T, T>>>(noff, bsum, CN, CE);
    k_scan_block<<<CG / 256, 256>>>(gcnt, goff, gbsum, CG);
    k_scan_partials<<<1, 1024>>>(gbsum, CG / 256);
    k_scan_add<<<(CG + T - 1) / T, T>>>(goff, gbsum, CG, CN);
    k_csr_scatter<<<(CE + T - 1) / T, T>>>(src, dst, dinv, noff, cur, csrc, cw);

    // ---- layer1 BN consts ----
    k_bnprep<<<(DH + T - 1) / T, T>>>(g1, be1, m1, v1, bns, bnsh, DH);

    // ---- layer 1: aggregate (fp32 in, fp16 out) then GEMM (bias+relu+BN1) ----
    k_agg_csr_f<<<CN / 4, 128>>>(x, agg1, noff, csrc, cw, dinv);
    {
        dim3 grid(DH / 128, CN / 128);
        k_hgemm<1, true><<<grid, 256>>>(agg1, wp1, h1, CN, DIN, DH, b1, bns, bnsh);
    }

    // re-prep BN consts for layers 2 & 3
    k_bnprep<<<(DH + T - 1) / T, T>>>(g2, be2, m2, v2, bns, bnsh, DH);
    k_bnprep<<<(DOUTD + T - 1) / T, T>>>(g3, be3, m3, v3, bns + DH, bnsh + DH, DOUTD);

    // ---- layer 2 (agg-first): agg(h1) fp16 -> GEMM2 with fused bias+relu+BN2 ----
    k_agg_csr_h<DH, false, true><<<CN, 128>>>(h1, ah1, noff, csrc, cw, dinv,
                                              nullptr, nullptr, nullptr);
    {
        dim3 grid(DH / 128, CN / 128);
        k_hgemm<1, true><<<grid, 256>>>(ah1, wp2, a2, CN, DH, DH, b2, bns, bnsh);
    }

    // ---- layer 3: GEMM (fp16 out) then aggregate (fp16 in, fused BN3, fp32 out) ----
    {
        dim3 grid(DOUTD / 128, CN / 128);
        k_hgemm<0, true><<<grid, 256>>>(a2, wp3, t3, CN, DH, DOUTD, nullptr, nullptr, nullptr);
    }
    k_agg_csr_h<DOUTD, true, false><<<CN / 2, 128>>>(t3, a3, noff, csrc, cw, dinv,
                                                     b3, bns + DH, bnsh + DH);

    // ---- segment mean pool (fp16 out) ----
    k_pool_seg<<<CG / 2, 128>>>(a3, goff, pool);

    // ---- MLP head ----
    {
        dim3 grid(DOUTD / 128, CG / 128);
        k_hgemm<2, true><<<grid, 256>>>(pool, wpf1, mlp1, CG, DOUTD, DOUTD, bf1, nullptr, nullptr);
        k_hgemm<3, false><<<grid, 256>>>(mlp1, wpf2, out, CG, DOUTD, DOUTD, bf2, nullptr, nullptr);
    }
}

// round 13
// speedup vs baseline: 1.1850x; 1.0293x over previous
#include <cuda_runtime.h>
#include <cuda_fp16.h>
#include <math.h>
#include <stdint.h>

#define CN 131072
#define CE 524288
#define CG 4096
#define DIN 128
#define DH  512
#define DOUTD 256
#define BN_EPS 1e-5f

// ---------------- scratch (static device globals; no allocation) -------------
__device__ float g_dinv[CN];
__device__ int   g_cnt [CN];
__device__ int   g_noff[CN + 1];
__device__ int   g_cur [CN];
__device__ int   g_bsum[512];
__device__ int   g_csrc[CE];
__device__ float g_cw  [CE];
__device__ int   g_gcnt[CG];
__device__ int   g_goff[CG + 1];
__device__ int   g_gbsum[16];
__device__ float g_bns [2 * DH + DOUTD];   // [0:DH) L1, [DH:2DH) L2, [2DH:+DOUT) L3
__device__ float g_bnsh[2 * DH + DOUTD];
__device__ __half g_xh  [(size_t)CN * DIN];     // x in fp16
__device__ __half g_agg1[(size_t)CN * DIN];     // GEMM1 A (fp16)
__device__ __half g_h1  [(size_t)CN * DH];      // GEMM1 out (fp16)
__device__ __half g_ah1 [(size_t)CN * DH];      // agg(h1) = GEMM2 A (fp16)
__device__ __half g_a2  [(size_t)CN * DH];      // GEMM2 out = GEMM3 A (fp16)
__device__ __half g_t3  [(size_t)CN * DOUTD];   // GEMM3 out (fp16, gathered)
__device__ __half g_a3  [(size_t)CN * DOUTD];   // layer3 out (fp16) -> pool
__device__ __half g_pool[(size_t)CG * DOUTD];
__device__ __half g_mlp1[(size_t)CG * DOUTD];
// fp16 k-pair-packed weights
__device__ uint32_t g_wp1 [(DIN / 2) * DH];
__device__ uint32_t g_wp2 [(DH / 2) * DH];
__device__ uint32_t g_wp3 [(DH / 2) * DOUTD];
__device__ uint32_t g_wpf1[(DOUTD / 2) * DOUTD];
__device__ uint32_t g_wpf2[(DOUTD / 2) * DOUTD];

// ---------------- fused prep kernels ------------------------------------------
__global__ void k_zero_all(int* __restrict__ cnt, int* __restrict__ cur,
                           int* __restrict__ gcnt) {
    unsigned i = blockIdx.x * blockDim.x + threadIdx.x;
    if (i < CN) { cnt[i] = 0; cur[i] = 0; }
    if (i < CG) gcnt[i] = 0;
}

__global__ void k_hist_all(const int* __restrict__ dst, const int* __restrict__ batch,
                           int* __restrict__ cnt, int* __restrict__ gcnt) {
    unsigned i = blockIdx.x * blockDim.x + threadIdx.x;
    if (i < CE) atomicAdd(&cnt[dst[i]], 1);
    else if (i < CE + CN) atomicAdd(&gcnt[batch[i - CE]], 1);
}

// exclusive block scan; optionally emits dinv = rsqrt(in+1)
__global__ void k_scan_block(const int* __restrict__ in, int* __restrict__ out,
                             int* __restrict__ bsum, int n, float* __restrict__ dinv) {
    __shared__ int sh[256];
    int t = threadIdx.x;
    int i = blockIdx.x * 256 + t;
    int v = (i < n) ? in[i] : 0;
    if (dinv && i < n) dinv[i] = rsqrtf((float)(v + 1));
    sh[t] = v; __syncthreads();
#pragma unroll
    for (int o = 1; o < 256; o <<= 1) {
        int x = (t >= o) ? sh[t - o] : 0;
        __syncthreads();
        sh[t] += x;
        __syncthreads();
    }
    if (i < n) out[i] = sh[t] - v;
    if (t == 255) bsum[blockIdx.x] = sh[255];
}

__global__ void k_scan_partials(int* __restrict__ bsum, int nb) {
    __shared__ int sh[1024];
    int t = threadIdx.x;
    int v = (t < nb) ? bsum[t] : 0;
    sh[t] = v; __syncthreads();
#pragma unroll
    for (int o = 1; o < 1024; o <<= 1) {
        int x = (t >= o) ? sh[t - o] : 0;
        __syncthreads();
        sh[t] += x;
        __syncthreads();
    }
    if (t < nb) bsum[t] = sh[t] - v;
}

__global__ void k_scan_add(int* __restrict__ out, const int* __restrict__ bsum,
                           int n, int total) {
    unsigned i = blockIdx.x * blockDim.x + threadIdx.x;
    if (i < (unsigned)n) out[i] += bsum[i >> 8];
    if (i == 0) out[n] = total;
}

__global__ void k_csr_scatter(const int* __restrict__ src, const int* __restrict__ dst,
                              const float* __restrict__ dinv,
                              const int* __restrict__ noff, int* __restrict__ cur,
                              int* __restrict__ csrc, float* __restrict__ cw) {
    unsigned e = blockIdx.x * blockDim.x + threadIdx.x;
    if (e >= CE) return;
    int d = dst[e], s = src[e];
    int pos = noff[d] + atomicAdd(&cur[d], 1);
    csrc[pos] = s;
    cw[pos] = dinv[s] * dinv[d];
}

// all 3 BN layers in one launch (disjoint slots)
__global__ void k_bnprep_all(
    const float* g1, const float* be1, const float* m1, const float* v1,
    const float* g2, const float* be2, const float* m2, const float* v2,
    const float* g3, const float* be3, const float* m3, const float* v3,
    float* __restrict__ s, float* __restrict__ sh) {
    unsigned i = blockIdx.x * blockDim.x + threadIdx.x;
    if (i >= 2 * DH + DOUTD) return;
    const float *g, *be, *m, *v;
    unsigned j;
    if (i < DH)           { g = g1; be = be1; m = m1; v = v1; j = i; }
    else if (i < 2 * DH)  { g = g2; be = be2; m = m2; v = v2; j = i - DH; }
    else                  { g = g3; be = be3; m = m3; v = v3; j = i - 2 * DH; }
    float sc = g[j] * rsqrtf(v[j] + BN_EPS);
    s[i] = sc;
    sh[i] = be[j] - m[j] * sc;
}

// all 5 weight packs in one launch
__global__ void k_wpack_all(
    const float* W1, const float* W2, const float* W3,
    const float* Wf1, const float* Wf2,
    uint32_t* wp1, uint32_t* wp2, uint32_t* wp3,
    uint32_t* wpf1, uint32_t* wpf2) {
    constexpr unsigned S1 = (DIN / 2) * DH;          // 32768
    constexpr unsigned S2 = S1 + (DH / 2) * DH;      // +131072
    constexpr unsigned S3 = S2 + (DH / 2) * DOUTD;   // +65536
    constexpr unsigned S4 = S3 + (DOUTD / 2) * DOUTD;
    constexpr unsigned S5 = S4 + (DOUTD / 2) * DOUTD;
    unsigned i = blockIdx.x * blockDim.x + threadIdx.x;
    if (i >= S5) return;
    const float* W; uint32_t* Wp; unsigned idx, N;
    if (i < S1)      { W = W1;  Wp = wp1;  idx = i;      N = DH; }
    else if (i < S2) { W = W2;  Wp = wp2;  idx = i - S1; N = DH; }
    else if (i < S3) { W = W3;  Wp = wp3;  idx = i - S2; N = DOUTD; }
    else if (i < S4) { W = Wf1; Wp = wpf1; idx = i - S3; N = DOUTD; }
    else             { W = Wf2; Wp = wpf2; idx = i - S4; N = DOUTD; }
    unsigned k2 = idx / N, n = idx % N;
    __half2 h = __floats2half2_rn(W[(size_t)(2 * k2) * N + n],
                                  W[(size_t)(2 * k2 + 1) * N + n]);
    Wp[idx] = *reinterpret_cast<uint32_t*>(&h);
}

// x fp32 -> fp16
__global__ void k_xhalf(const float* __restrict__ x, __half* __restrict__ xh) {
    unsigned i = blockIdx.x * blockDim.x + threadIdx.x;
    if (i >= (unsigned)CN * DIN / 2) return;
    __half2 h = __floats2half2_rn(x[2 * i], x[2 * i + 1]);
    *reinterpret_cast<__half2*>(xh + 2 * i) = h;
}

// ---------------- CSR aggregation: fp16 in/out, TPN = D/4 ---------------------
template <int D, bool BN, bool OH>
__global__ __launch_bounds__(128) void k_agg_csr_h(
    const __half* __restrict__ t, void* __restrict__ out,
    const int* __restrict__ noff, const int* __restrict__ csrc,
    const float* __restrict__ cw, const float* __restrict__ dinv,
    const float* __restrict__ bias, const float* __restrict__ bns,
    const float* __restrict__ bnsh) {
    constexpr int TPN = D / 4;
    constexpr int NPB = 128 / TPN;
    int node = blockIdx.x * NPB + threadIdx.x / TPN;
    int lane = threadIdx.x % TPN;
    int c = lane * 4;

    float di = dinv[node];
    float w0 = di * di;
    float a0, a1, a2v, a3v;
    {
        uint2 raw = *reinterpret_cast<const uint2*>(t + (size_t)node * D + c);
        float2 f0 = __half22float2(*reinterpret_cast<__half2*>(&raw.x));
        float2 f1 = __half22float2(*reinterpret_cast<__half2*>(&raw.y));
        a0 = f0.x * w0; a1 = f0.y * w0; a2v = f1.x * w0; a3v = f1.y * w0;
    }

    int beg = noff[node], end = noff[node + 1];
    for (int p = beg; p < end; p++) {
        int s = csrc[p];
        float w = cw[p];
        uint2 raw = *reinterpret_cast<const uint2*>(t + (size_t)s * D + c);
        float2 f0 = __half22float2(*reinterpret_cast<__half2*>(&raw.x));
        float2 f1 = __half22float2(*reinterpret_cast<__half2*>(&raw.y));
        a0 += f0.x * w; a1 += f0.y * w; a2v += f1.x * w; a3v += f1.y * w;
    }

    if (BN) {
        float4 b = *reinterpret_cast<const float4*>(bias + c);
        float4 s4 = *reinterpret_cast<const float4*>(bns + c);
        float4 h4 = *reinterpret_cast<const float4*>(bnsh + c);
        a0 = fmaxf(a0 + b.x, 0.0f) * s4.x + h4.x;
        a1 = fmaxf(a1 + b.y, 0.0f) * s4.y + h4.y;
        a2v = fmaxf(a2v + b.z, 0.0f) * s4.z + h4.z;
        a3v = fmaxf(a3v + b.w, 0.0f) * s4.w + h4.w;
    }
    if (OH) {
        uint2 o;
        __half2 h0 = __floats2half2_rn(a0, a1);
        __half2 h1 = __floats2half2_rn(a2v, a3v);
        o.x = *reinterpret_cast<uint32_t*>(&h0);
        o.y = *reinterpret_cast<uint32_t*>(&h1);
        *reinterpret_cast<uint2*>((__half*)out + (size_t)node * D + c) = o;
    } else {
        *reinterpret_cast<float4*>((float*)out + (size_t)node * D + c) =
            make_float4(a0, a1, a2v, a3v);
    }
}

// ---------------- segment mean pool (fp16 in, fp16 out) -----------------------
__global__ __launch_bounds__(128) void k_pool_seg(const __half* __restrict__ h,
                                                  const int* __restrict__ goff,
                                                  __half* __restrict__ pooled) {
    int g = blockIdx.x * 2 + threadIdx.x / 64;
    int lane = threadIdx.x % 64;
    int c = lane * 4;
    int beg = goff[g], end = goff[g + 1];
    float a0 = 0.f, a1 = 0.f, a2v = 0.f, a3v = 0.f;
    for (int n = beg; n < end; n++) {
        uint2 raw = *reinterpret_cast<const uint2*>(h + (size_t)n * DOUTD + c);
        float2 f0 = __half22float2(*reinterpret_cast<__half2*>(&raw.x));
        float2 f1 = __half22float2(*reinterpret_cast<__half2*>(&raw.y));
        a0 += f0.x; a1 += f0.y; a2v += f1.x; a3v += f1.y;
    }
    float inv = 1.0f / fmaxf((float)(end - beg), 1.0f);
    uint2 o;
    __half2 h0 = __floats2half2_rn(a0 * inv, a1 * inv);
    __half2 h1 = __floats2half2_rn(a2v * inv, a3v * inv);
    o.x = *reinterpret_cast<uint32_t*>(&h0);
    o.y = *reinterpret_cast<uint32_t*>(&h1);
    *reinterpret_cast<uint2*>(pooled + (size_t)g * DOUTD + c) = o;
}

// ---------------- FP16 tensor-core GEMM (double-buffered) ---------------------
__device__ __forceinline__ void mma_f16(float* c, const uint32_t* a, const uint32_t* b) {
    asm volatile(
        "mma.sync.aligned.m16n8k16.row.col.f32.f16.f16.f32 "
        "{%0,%1,%2,%3}, {%4,%5,%6,%7}, {%8,%9}, {%0,%1,%2,%3};"
        : "+f"(c[0]), "+f"(c[1]), "+f"(c[2]), "+f"(c[3])
        : "r"(a[0]), "r"(a[1]), "r"(a[2]), "r"(a[3]), "r"(b[0]), "r"(b[1]));
}

#define GSTRIDE 136

// EPI: 0=none, 1=bias+relu+BN, 2=bias+relu, 3=bias ; OH: fp16 output
template <int EPI, bool OH>
__global__ __launch_bounds__(256, 2) void k_hgemm(
    const __half* __restrict__ A, const uint32_t* __restrict__ Wp, void* __restrict__ C,
    int M, int K, int Nn,
    const float* __restrict__ bias, const float* __restrict__ bns,
    const float* __restrict__ bnsh) {
    __shared__ uint32_t As[2][16][GSTRIDE];
    __shared__ uint32_t Bs[2][16][GSTRIDE];

    const int tid = threadIdx.x;
    const int bc = blockIdx.x, br = blockIdx.y;
    const int lane = tid & 31;
    const int wid = tid >> 5;
    const int wm = (wid >> 2) * 64;
    const int wn = (wid & 3) * 32;

    const int arow = tid >> 1;
    const int ak2 = (tid & 1) * 8;
    const int bn4 = (tid & 31) * 4;
    const int brow = tid >> 5;

    const int K2 = K >> 1;
    const uint32_t* Aptr = reinterpret_cast<const uint32_t*>(A)
                           + (size_t)(br * 128 + arow) * K2 + ak2;
    const uint32_t* Bptr = Wp + (size_t)brow * Nn + bc * 128 + bn4;
    const size_t BchunkStep = (size_t)16 * Nn;

    float acc[4][4][4];
#pragma unroll
    for (int mf = 0; mf < 4; mf++)
#pragma unroll
        for (int nf = 0; nf < 4; nf++)
#pragma unroll
            for (int r = 0; r < 4; r++) acc[mf][nf][r] = 0.0f;

    const int nchunks = K >> 5;

    uint4 ra0, ra1, rb0, rb1;
    ra0 = *reinterpret_cast<const uint4*>(Aptr);
    ra1 = *reinterpret_cast<const uint4*>(Aptr + 4);
    rb0 = *reinterpret_cast<const uint4*>(Bptr);
    rb1 = *reinterpret_cast<const uint4*>(Bptr + 8 * Nn);
    {
        As[0][ak2 + 0][arow] = ra0.x; As[0][ak2 + 1][arow] = ra0.y;
        As[0][ak2 + 2][arow] = ra0.z; As[0][ak2 + 3][arow] = ra0.w;
        As[0][ak2 + 4][arow] = ra1.x; As[0][ak2 + 5][arow] = ra1.y;
        As[0][ak2 + 6][arow] = ra1.z; As[0][ak2 + 7][arow] = ra1.w;
        *reinterpret_cast<uint4*>(&Bs[0][brow][bn4]) = rb0;
        *reinterpret_cast<uint4*>(&Bs[0][brow + 8][bn4]) = rb1;
    }
    __syncthreads();

    const int gr = lane >> 2;
    const int gc = lane & 3;

    for (int i = 0; i < nchunks; i++) {
        if (i + 1 < nchunks) {
            const uint32_t* Ap = Aptr + (i + 1) * 16;
            const uint32_t* Bp = Bptr + (size_t)(i + 1) * BchunkStep;
            ra0 = *reinterpret_cast<const uint4*>(Ap);
            ra1 = *reinterpret_cast<const uint4*>(Ap + 4);
            rb0 = *reinterpret_cast<const uint4*>(Bp);
            rb1 = *reinterpret_cast<const uint4*>(Bp + 8 * Nn);
        }

        const int cb = i & 1;
#pragma unroll
        for (int ks2 = 0; ks2 < 16; ks2 += 8) {
            uint32_t af[4][4];
#pragma unroll
            for (int mf = 0; mf < 4; mf++) {
                int mb = wm + mf * 16;
                af[mf][0] = As[cb][ks2 + gc][mb + gr];
                af[mf][1] = As[cb][ks2 + gc][mb + gr + 8];
                af[mf][2] = As[cb][ks2 + gc + 4][mb + gr];
                af[mf][3] = As[cb][ks2 + gc + 4][mb + gr + 8];
            }
            uint32_t bf[4][2];
#pragma unroll
            for (int nf = 0; nf < 4; nf++) {
                int nb = wn + nf * 8;
                bf[nf][0] = Bs[cb][ks2 + gc][nb + gr];
                bf[nf][1] = Bs[cb][ks2 + gc + 4][nb + gr];
            }
#pragma unroll
            for (int mf = 0; mf < 4; mf++)
#pragma unroll
                for (int nf = 0; nf < 4; nf++)
                    mma_f16(acc[mf][nf], af[mf], bf[nf]);
        }

        if (i + 1 < nchunks) {
            const int nb2 = (i + 1) & 1;
            As[nb2][ak2 + 0][arow] = ra0.x; As[nb2][ak2 + 1][arow] = ra0.y;
            As[nb2][ak2 + 2][arow] = ra0.z; As[nb2][ak2 + 3][arow] = ra0.w;
            As[nb2][ak2 + 4][arow] = ra1.x; As[nb2][ak2 + 5][arow] = ra1.y;
            As[nb2][ak2 + 6][arow] = ra1.z; As[nb2][ak2 + 7][arow] = ra1.w;
            *reinterpret_cast<uint4*>(&Bs[nb2][brow][bn4]) = rb0;
            *reinterpret_cast<uint4*>(&Bs[nb2][brow + 8][bn4]) = rb1;
        }
        __syncthreads();
    }

    float* Cf = reinterpret_cast<float*>(C);
    __half* Ch = reinterpret_cast<__half*>(C);
#pragma unroll
    for (int nf = 0; nf < 4; nf++) {
        int col = bc * 128 + wn + nf * 8 + gc * 2;
        float bb0 = 0.f, bb1 = 0.f, s0 = 1.f, s1 = 1.f, h0 = 0.f, h1 = 0.f;
        if (EPI != 0) { bb0 = bias[col]; bb1 = bias[col + 1]; }
        if (EPI == 1) {
            s0 = bns[col]; s1 = bns[col + 1];
            h0 = bnsh[col]; h1 = bnsh[col + 1];
        }
#pragma unroll
        for (int mf = 0; mf < 4; mf++) {
            int row0 = br * 128 + wm + mf * 16 + gr;
            float v0 = acc[mf][nf][0], v1 = acc[mf][nf][1];
            float v2 = acc[mf][nf][2], v3 = acc[mf][nf][3];
            if (EPI != 0) { v0 += bb0; v1 += bb1; v2 += bb0; v3 += bb1; }
            if (EPI == 1 || EPI == 2) {
                v0 = fmaxf(v0, 0.f); v1 = fmaxf(v1, 0.f);
                v2 = fmaxf(v2, 0.f); v3 = fmaxf(v3, 0.f);
            }
            if (EPI == 1) {
                v0 = v0 * s0 + h0; v1 = v1 * s1 + h1;
                v2 = v2 * s0 + h0; v3 = v3 * s1 + h1;
            }
            if (OH) {
                *reinterpret_cast<__half2*>(Ch + (size_t)row0 * Nn + col) =
                    __floats2half2_rn(v0, v1);
                *reinterpret_cast<__half2*>(Ch + (size_t)(row0 + 8) * Nn + col) =
                    __floats2half2_rn(v2, v3);
            } else {
                *reinterpret_cast<float2*>(Cf + (size_t)row0 * Nn + col) = make_float2(v0, v1);
                *reinterpret_cast<float2*>(Cf + (size_t)(row0 + 8) * Nn + col) = make_float2(v2, v3);
            }
        }
    }
}

// ---------------- launch -----------------------------------------------------
extern "C" void kernel_launch(void* const* d_in, const int* in_sizes, int n_in,
                              void* d_out, int out_size) {
    const float* x   = (const float*)d_in[0];
    const int* ei    = (const int*)d_in[1];
    const int* batch = (const int*)d_in[2];
    const float* W1  = (const float*)d_in[3];  const float* b1  = (const float*)d_in[4];
    const float* W2  = (const float*)d_in[5];  const float* b2  = (const float*)d_in[6];
    const float* W3  = (const float*)d_in[7];  const float* b3  = (const float*)d_in[8];
    const float* g1  = (const float*)d_in[9];  const float* be1 = (const float*)d_in[10];
    const float* m1  = (const float*)d_in[11]; const float* v1  = (const float*)d_in[12];
    const float* g2  = (const float*)d_in[13]; const float* be2 = (const float*)d_in[14];
    const float* m2  = (const float*)d_in[15]; const float* v2  = (const float*)d_in[16];
    const float* g3  = (const float*)d_in[17]; const float* be3 = (const float*)d_in[18];
    const float* m3  = (const float*)d_in[19]; const float* v3  = (const float*)d_in[20];
    const float* Wf1 = (const float*)d_in[21]; const float* bf1 = (const float*)d_in[22];
    const float* Wf2 = (const float*)d_in[23]; const float* bf2 = (const float*)d_in[24];
    float* out = (float*)d_out;

    const int* src = ei;
    const int* dst = ei + CE;

    float *dinv, *cw, *bns, *bnsh;
    __half *xh, *agg1, *h1, *ah1, *a2, *t3, *a3, *pool, *mlp1;
    uint32_t *wp1, *wp2, *wp3, *wpf1, *wpf2;
    int *cnt, *noff, *cur, *bsum, *csrc, *gcnt, *goff, *gbsum;
    cudaGetSymbolAddress((void**)&dinv, g_dinv);
    cudaGetSymbolAddress((void**)&cnt,  g_cnt);
    cudaGetSymbolAddress((void**)&noff, g_noff);
    cudaGetSymbolAddress((void**)&cur,  g_cur);
    cudaGetSymbolAddress((void**)&bsum, g_bsum);
    cudaGetSymbolAddress((void**)&csrc, g_csrc);
    cudaGetSymbolAddress((void**)&cw,   g_cw);
    cudaGetSymbolAddress((void**)&gcnt, g_gcnt);
    cudaGetSymbolAddress((void**)&goff, g_goff);
    cudaGetSymbolAddress((void**)&gbsum, g_gbsum);
    cudaGetSymbolAddress((void**)&bns,  g_bns);
    cudaGetSymbolAddress((void**)&bnsh, g_bnsh);
    cudaGetSymbolAddress((void**)&xh,   g_xh);
    cudaGetSymbolAddress((void**)&agg1, g_agg1);
    cudaGetSymbolAddress((void**)&h1,   g_h1);
    cudaGetSymbolAddress((void**)&ah1,  g_ah1);
    cudaGetSymbolAddress((void**)&a2,   g_a2);
    cudaGetSymbolAddress((void**)&t3,   g_t3);
    cudaGetSymbolAddress((void**)&a3,   g_a3);
    cudaGetSymbolAddress((void**)&pool, g_pool);
    cudaGetSymbolAddress((void**)&mlp1, g_mlp1);
    cudaGetSymbolAddress((void**)&wp1,  g_wp1);
    cudaGetSymbolAddress((void**)&wp2,  g_wp2);
    cudaGetSymbolAddress((void**)&wp3,  g_wp3);
    cudaGetSymbolAddress((void**)&wpf1, g_wpf1);
    cudaGetSymbolAddress((void**)&wpf2, g_wpf2);

    const int T = 256;

    // ---- fused prep: weight pack, x->fp16, BN consts ----
    {
        unsigned npack = (DIN / 2) * DH + (DH / 2) * DH + (DH / 2) * DOUTD
                       + 2 * (DOUTD / 2) * DOUTD;
        k_wpack_all<<<(npack + T - 1) / T, T>>>(W1, W2, W3, Wf1, Wf2,
                                                wp1, wp2, wp3, wpf1, wpf2);
    }
    k_xhalf<<<((unsigned)CN * DIN / 2 + T - 1) / T, T>>>(x, xh);
    k_bnprep_all<<<(2 * DH + DOUTD + T - 1) / T, T>>>(
        g1, be1, m1, v1, g2, be2, m2, v2, g3, be3, m3, v3, bns, bnsh);

    // ---- CSR build ----
    k_zero_all<<<(CN + T - 1) / T, T>>>(cnt, cur, gcnt);
    k_hist_all<<<(CE + CN + T - 1) / T, T>>>(dst, batch, cnt, gcnt);
    k_scan_block<<<CN / 256, 256>>>(cnt, noff, bsum, CN, dinv);
    k_scan_partials<<<1, 1024>>>(bsum, CN / 256);
    k_scan_add<<<(CN + T - 1) / T, T>>>(noff, bsum, CN, CE);
    k_scan_block<<<CG / 256, 256>>>(gcnt, goff, gbsum, CG, nullptr);
    k_scan_partials<<<1, 1024>>>(gbsum, CG / 256);
    k_scan_add<<<(CG + T - 1) / T, T>>>(goff, gbsum, CG, CN);
    k_csr_scatter<<<(CE + T - 1) / T, T>>>(src, dst, dinv, noff, cur, csrc, cw);

    // ---- layer 1: aggregate x (fp16) then GEMM (bias+relu+BN1) ----
    k_agg_csr_h<DIN, false, true><<<CN / 4, 128>>>(xh, agg1, noff, csrc, cw, dinv,
                                                   nullptr, nullptr, nullptr);
    {
        dim3 grid(DH / 128, CN / 128);
        k_hgemm<1, true><<<grid, 256>>>(agg1, wp1, h1, CN, DIN, DH, b1, bns, bnsh);
    }

    // ---- layer 2 (agg-first): agg(h1) -> GEMM2 with fused bias+relu+BN2 ----
    k_agg_csr_h<DH, false, true><<<CN, 128>>>(h1, ah1, noff, csrc, cw, dinv,
                                              nullptr, nullptr, nullptr);
    {
        dim3 grid(DH / 128, CN / 128);
        k_hgemm<1, true><<<grid, 256>>>(ah1, wp2, a2, CN, DH, DH, b2,
                                        bns + DH, bnsh + DH);
    }

    // ---- layer 3: GEMM (fp16 out) then aggregate (fused BN3, fp16 out) ----
    {
        dim3 grid(DOUTD / 128, CN / 128);
        k_hgemm<0, true><<<grid, 256>>>(a2, wp3, t3, CN, DH, DOUTD, nullptr, nullptr, nullptr);
    }
    k_agg_csr_h<DOUTD, true, true><<<CN / 2, 128>>>(t3, a3, noff, csrc, cw, dinv,
                                                    b3, bns + 2 * DH, bnsh + 2 * DH);

    // ---- segment mean pool (fp16 in/out) ----
    k_pool_seg<<<CG / 2, 128>>>(a3, goff, pool);

    // ---- MLP head ----
    {
        dim3 grid(DOUTD / 128, CG / 128);
        k_hgemm<2, true><<<grid, 256>>>(pool, wpf1, mlp1, CG, DOUTD, DOUTD, bf1, nullptr, nullptr);
        k_hgemm<3, false><<<grid, 256>>>(mlp1, wpf2, out, CG, DOUTD, DOUTD, bf2, nullptr, nullptr);
    }
}

// round 15
// speedup vs baseline: 1.1891x; 1.0035x over previous
#include <cuda_runtime.h>
#include <cuda_fp16.h>
#include <math.h>
#include <stdint.h>

#define CN 131072
#define CE 524288
#define CG 4096
#define DIN 128
#define DH  512
#define DOUTD 256
#define BN_EPS 1e-5f

// ---------------- scratch (static device globals; no allocation) -------------
__device__ float g_dinv[CN];
__device__ int   g_cnt [CN];
__device__ int   g_noff[CN + 1];
__device__ int   g_cur [CN];
__device__ int   g_bsum[512];
__device__ int   g_csrc[CE];
__device__ float g_cw  [CE];
__device__ int   g_gcnt[CG];
__device__ int   g_goff[CG + 1];
__device__ int   g_gbsum[16];
__device__ float g_bns [2 * DH + DOUTD];
__device__ float g_bnsh[2 * DH + DOUTD];
__device__ __half g_xh  [(size_t)CN * DIN];
__device__ __half g_agg1[(size_t)CN * DIN];
__device__ __half g_h1  [(size_t)CN * DH];
__device__ __half g_ah1 [(size_t)CN * DH];
__device__ __half g_a2  [(size_t)CN * DH];
__device__ __half g_t3  [(size_t)CN * DOUTD];
__device__ __half g_a3  [(size_t)CN * DOUTD];
__device__ __half g_pool[(size_t)CG * DOUTD];
__device__ __half g_mlp1[(size_t)CG * DOUTD];
__device__ uint32_t g_wp1 [(DIN / 2) * DH];
__device__ uint32_t g_wp2 [(DH / 2) * DH];
__device__ uint32_t g_wp3 [(DH / 2) * DOUTD];
__device__ uint32_t g_wpf1[(DOUTD / 2) * DOUTD];
__device__ uint32_t g_wpf2[(DOUTD / 2) * DOUTD];

// ---------------- fused prep: wpack x5 + x->fp16 + bnprep x3 + zero ----------
#define NB_WPACK 1152u     // 294912 / 256
#define NB_XH    32768u    // CN*DIN/2 / 256
#define NB_BN    5u        // 1280 / 256
#define NB_ZERO  512u      // CN / 256

__global__ void k_prep_all(
    const float* x, __half* xh,
    const float* W1, const float* W2, const float* W3,
    const float* Wf1, const float* Wf2,
    uint32_t* wp1, uint32_t* wp2, uint32_t* wp3, uint32_t* wpf1, uint32_t* wpf2,
    const float* g1, const float* be1, const float* m1, const float* v1,
    const float* g2, const float* be2, const float* m2, const float* v2,
    const float* g3, const float* be3, const float* m3, const float* v3,
    float* bns, float* bnsh,
    int* cnt, int* cur, int* gcnt) {
    unsigned b = blockIdx.x;
    unsigned t = threadIdx.x;
    if (b < NB_WPACK) {
        constexpr unsigned S1 = (DIN / 2) * DH;
        constexpr unsigned S2 = S1 + (DH / 2) * DH;
        constexpr unsigned S3 = S2 + (DH / 2) * DOUTD;
        constexpr unsigned S4 = S3 + (DOUTD / 2) * DOUTD;
        constexpr unsigned S5 = S4 + (DOUTD / 2) * DOUTD;
        unsigned i = b * 256 + t;
        if (i >= S5) return;
        const float* W; uint32_t* Wp; unsigned idx, N;
        if (i < S1)      { W = W1;  Wp = wp1;  idx = i;      N = DH; }
        else if (i < S2) { W = W2;  Wp = wp2;  idx = i - S1; N = DH; }
        else if (i < S3) { W = W3;  Wp = wp3;  idx = i - S2; N = DOUTD; }
        else if (i < S4) { W = Wf1; Wp = wpf1; idx = i - S3; N = DOUTD; }
        else             { W = Wf2; Wp = wpf2; idx = i - S4; N = DOUTD; }
        unsigned k2 = idx / N, n = idx % N;
        __half2 h = __floats2half2_rn(W[(size_t)(2 * k2) * N + n],
                                      W[(size_t)(2 * k2 + 1) * N + n]);
        Wp[idx] = *reinterpret_cast<uint32_t*>(&h);
    } else if (b < NB_WPACK + NB_XH) {
        unsigned i = (b - NB_WPACK) * 256 + t;   // < CN*DIN/2 exactly
        __half2 h = __floats2half2_rn(x[2 * i], x[2 * i + 1]);
        *reinterpret_cast<__half2*>(xh + 2 * (size_t)i) = h;
    } else if (b < NB_WPACK + NB_XH + NB_BN) {
        unsigned i = (b - NB_WPACK - NB_XH) * 256 + t;
        if (i >= 2 * DH + DOUTD) return;
        const float *g, *be, *m, *v;
        unsigned j;
        if (i < DH)          { g = g1; be = be1; m = m1; v = v1; j = i; }
        else if (i < 2 * DH) { g = g2; be = be2; m = m2; v = v2; j = i - DH; }
        else                 { g = g3; be = be3; m = m3; v = v3; j = i - 2 * DH; }
        float sc = g[j] * rsqrtf(v[j] + BN_EPS);
        bns[i] = sc;
        bnsh[i] = be[j] - m[j] * sc;
    } else {
        unsigned i = (b - NB_WPACK - NB_XH - NB_BN) * 256 + t;  // < CN
        cnt[i] = 0; cur[i] = 0;
        if (i < CG) gcnt[i] = 0;
    }
}

__global__ void k_hist_all(const int* __restrict__ dst, const int* __restrict__ batch,
                           int* __restrict__ cnt, int* __restrict__ gcnt) {
    unsigned i = blockIdx.x * blockDim.x + threadIdx.x;
    if (i < CE) atomicAdd(&cnt[dst[i]], 1);
    else if (i < CE + CN) atomicAdd(&gcnt[batch[i - CE]], 1);
}

// merged exclusive block scans: blocks [0,512) nodes (+dinv), [512,528) graphs
__global__ void k_scan_block2(const int* __restrict__ cnt, int* __restrict__ noff,
                              int* __restrict__ bsum, const int* __restrict__ gcnt,
                              int* __restrict__ goff, int* __restrict__ gbsum,
                              float* __restrict__ dinv) {
    __shared__ int sh[256];
    int t = threadIdx.x;
    int b = blockIdx.x;
    const int* in; int* outp; int* bs; int base;
    if (b < 512) { in = cnt; outp = noff; bs = bsum; base = b; }
    else         { in = gcnt; outp = goff; bs = gbsum; base = b - 512; }
    int i = base * 256 + t;
    int v = in[i];
    if (b < 512) dinv[i] = rsqrtf((float)(v + 1));
    sh[t] = v; __syncthreads();
#pragma unroll
    for (int o = 1; o < 256; o <<= 1) {
        int x = (t >= o) ? sh[t - o] : 0;
        __syncthreads();
        sh[t] += x;
        __syncthreads();
    }
    outp[i] = sh[t] - v;
    if (t == 255) bs[base] = sh[255];
}

// merged partials scan: block 0 -> bsum(512), block 1 -> gbsum(16)
__global__ void k_scan_partials2(int* __restrict__ bsum, int* __restrict__ gbsum) {
    __shared__ int sh[1024];
    int t = threadIdx.x;
    int* p = (blockIdx.x == 0) ? bsum : gbsum;
    int nb = (blockIdx.x == 0) ? 512 : 16;
    int v = (t < nb) ? p[t] : 0;
    sh[t] = v; __syncthreads();
#pragma unroll
    for (int o = 1; o < 1024; o <<= 1) {
        int x = (t >= o) ? sh[t - o] : 0;
        __syncthreads();
        sh[t] += x;
        __syncthreads();
    }
    if (t < nb) p[t] = sh[t] - v;
}

__global__ void k_scan_add2(int* __restrict__ noff, const int* __restrict__ bsum,
                            int* __restrict__ goff, const int* __restrict__ gbsum) {
    unsigned i = blockIdx.x * blockDim.x + threadIdx.x;
    if (i < CN) {
        noff[i] += bsum[i >> 8];
        if (i == 0) noff[CN] = CE;
    } else if (i < CN + CG) {
        unsigned j = i - CN;
        goff[j] += gbsum[j >> 8];
        if (j == 0) goff[CG] = CN;
    }
}

__global__ void k_csr_scatter(const int* __restrict__ src, const int* __restrict__ dst,
                              const float* __restrict__ dinv,
                              const int* __restrict__ noff, int* __restrict__ cur,
                              int* __restrict__ csrc, float* __restrict__ cw) {
    unsigned e = blockIdx.x * blockDim.x + threadIdx.x;
    if (e >= CE) return;
    int d = dst[e], s = src[e];
    int pos = noff[d] + atomicAdd(&cur[d], 1);
    csrc[pos] = s;
    cw[pos] = dinv[s] * dinv[d];
}

// ---------------- CSR aggregation: fp16 in/out, TPN = D/4 ---------------------
template <int D, bool BN, bool OH>
__global__ __launch_bounds__(128) void k_agg_csr_h(
    const __half* __restrict__ t, void* __restrict__ out,
    const int* __restrict__ noff, const int* __restrict__ csrc,
    const float* __restrict__ cw, const float* __restrict__ dinv,
    const float* __restrict__ bias, const float* __restrict__ bns,
    const float* __restrict__ bnsh) {
    constexpr int TPN = D / 4;
    constexpr int NPB = 128 / TPN;
    int node = blockIdx.x * NPB + threadIdx.x / TPN;
    int lane = threadIdx.x % TPN;
    int c = lane * 4;

    float di = dinv[node];
    float w0 = di * di;
    float a0, a1, a2v, a3v;
    {
        uint2 raw = *reinterpret_cast<const uint2*>(t + (size_t)node * D + c);
        float2 f0 = __half22float2(*reinterpret_cast<__half2*>(&raw.x));
        float2 f1 = __half22float2(*reinterpret_cast<__half2*>(&raw.y));
        a0 = f0.x * w0; a1 = f0.y * w0; a2v = f1.x * w0; a3v = f1.y * w0;
    }

    int beg = noff[node], end = noff[node + 1];
    for (int p = beg; p < end; p++) {
        int s = csrc[p];
        float w = cw[p];
        uint2 raw = *reinterpret_cast<const uint2*>(t + (size_t)s * D + c);
        float2 f0 = __half22float2(*reinterpret_cast<__half2*>(&raw.x));
        float2 f1 = __half22float2(*reinterpret_cast<__half2*>(&raw.y));
        a0 += f0.x * w; a1 += f0.y * w; a2v += f1.x * w; a3v += f1.y * w;
    }

    if (BN) {
        float4 b = *reinterpret_cast<const float4*>(bias + c);
        float4 s4 = *reinterpret_cast<const float4*>(bns + c);
        float4 h4 = *reinterpret_cast<const float4*>(bnsh + c);
        a0 = fmaxf(a0 + b.x, 0.0f) * s4.x + h4.x;
        a1 = fmaxf(a1 + b.y, 0.0f) * s4.y + h4.y;
        a2v = fmaxf(a2v + b.z, 0.0f) * s4.z + h4.z;
        a3v = fmaxf(a3v + b.w, 0.0f) * s4.w + h4.w;
    }
    if (OH) {
        uint2 o;
        __half2 h0 = __floats2half2_rn(a0, a1);
        __half2 h1 = __floats2half2_rn(a2v, a3v);
        o.x = *reinterpret_cast<uint32_t*>(&h0);
        o.y = *reinterpret_cast<uint32_t*>(&h1);
        *reinterpret_cast<uint2*>((__half*)out + (size_t)node * D + c) = o;
    } else {
        *reinterpret_cast<float4*>((float*)out + (size_t)node * D + c) =
            make_float4(a0, a1, a2v, a3v);
    }
}

// ---------------- segment mean pool (fp16 in, fp16 out) -----------------------
__global__ __launch_bounds__(128) void k_pool_seg(const __half* __restrict__ h,
                                                  const int* __restrict__ goff,
                                                  __half* __restrict__ pooled) {
    int g = blockIdx.x * 2 + threadIdx.x / 64;
    int lane = threadIdx.x % 64;
    int c = lane * 4;
    int beg = goff[g], end = goff[g + 1];
    float a0 = 0.f, a1 = 0.f, a2v = 0.f, a3v = 0.f;
    for (int n = beg; n < end; n++) {
        uint2 raw = *reinterpret_cast<const uint2*>(h + (size_t)n * DOUTD + c);
        float2 f0 = __half22float2(*reinterpret_cast<__half2*>(&raw.x));
        float2 f1 = __half22float2(*reinterpret_cast<__half2*>(&raw.y));
        a0 += f0.x; a1 += f0.y; a2v += f1.x; a3v += f1.y;
    }
    float inv = 1.0f / fmaxf((float)(end - beg), 1.0f);
    uint2 o;
    __half2 h0 = __floats2half2_rn(a0 * inv, a1 * inv);
    __half2 h1 = __floats2half2_rn(a2v * inv, a3v * inv);
    o.x = *reinterpret_cast<uint32_t*>(&h0);
    o.y = *reinterpret_cast<uint32_t*>(&h1);
    *reinterpret_cast<uint2*>(pooled + (size_t)g * DOUTD + c) = o;
}

// ---------------- FP16 tensor-core GEMM (double-buffered) ---------------------
__device__ __forceinline__ void mma_f16(float* c, const uint32_t* a, const uint32_t* b) {
    asm volatile(
        "mma.sync.aligned.m16n8k16.row.col.f32.f16.f16.f32 "
        "{%0,%1,%2,%3}, {%4,%5,%6,%7}, {%8,%9}, {%0,%1,%2,%3};"
        : "+f"(c[0]), "+f"(c[1]), "+f"(c[2]), "+f"(c[3])
        : "r"(a[0]), "r"(a[1]), "r"(a[2]), "r"(a[3]), "r"(b[0]), "r"(b[1]));
}

#define GSTRIDE 136

template <int EPI, bool OH>
__global__ __launch_bounds__(256, 2) void k_hgemm(
    const __half* __restrict__ A, const uint32_t* __restrict__ Wp, void* __restrict__ C,
    int M, int K, int Nn,
    const float* __restrict__ bias, const float* __restrict__ bns,
    const float* __restrict__ bnsh) {
    __shared__ uint32_t As[2][16][GSTRIDE];
    __shared__ uint32_t Bs[2][16][GSTRIDE];

    const int tid = threadIdx.x;
    const int bc = blockIdx.x, br = blockIdx.y;
    const int lane = tid & 31;
    const int wid = tid >> 5;
    const int wm = (wid >> 2) * 64;
    const int wn = (wid & 3) * 32;

    const int arow = tid >> 1;
    const int ak2 = (tid & 1) * 8;
    const int bn4 = (tid & 31) * 4;
    const int brow = tid >> 5;

    const int K2 = K >> 1;
    const uint32_t* Aptr = reinterpret_cast<const uint32_t*>(A)
                           + (size_t)(br * 128 + arow) * K2 + ak2;
    const uint32_t* Bptr = Wp + (size_t)brow * Nn + bc * 128 + bn4;
    const size_t BchunkStep = (size_t)16 * Nn;

    float acc[4][4][4];
#pragma unroll
    for (int mf = 0; mf < 4; mf++)
#pragma unroll
        for (int nf = 0; nf < 4; nf++)
#pragma unroll
            for (int r = 0; r < 4; r++) acc[mf][nf][r] = 0.0f;

    const int nchunks = K >> 5;

    uint4 ra0, ra1, rb0, rb1;
    ra0 = *reinterpret_cast<const uint4*>(Aptr);
    ra1 = *reinterpret_cast<const uint4*>(Aptr + 4);
    rb0 = *reinterpret_cast<const uint4*>(Bptr);
    rb1 = *reinterpret_cast<const uint4*>(Bptr + 8 * Nn);
    {
        As[0][ak2 + 0][arow] = ra0.x; As[0][ak2 + 1][arow] = ra0.y;
        As[0][ak2 + 2][arow] = ra0.z; As[0][ak2 + 3][arow] = ra0.w;
        As[0][ak2 + 4][arow] = ra1.x; As[0][ak2 + 5][arow] = ra1.y;
        As[0][ak2 + 6][arow] = ra1.z; As[0][ak2 + 7][arow] = ra1.w;
        *reinterpret_cast<uint4*>(&Bs[0][brow][bn4]) = rb0;
        *reinterpret_cast<uint4*>(&Bs[0][brow + 8][bn4]) = rb1;
    }
    __syncthreads();

    const int gr = lane >> 2;
    const int gc = lane & 3;

    for (int i = 0; i < nchunks; i++) {
        if (i + 1 < nchunks) {
            const uint32_t* Ap = Aptr + (i + 1) * 16;
            const uint32_t* Bp = Bptr + (size_t)(i + 1) * BchunkStep;
            ra0 = *reinterpret_cast<const uint4*>(Ap);
            ra1 = *reinterpret_cast<const uint4*>(Ap + 4);
            rb0 = *reinterpret_cast<const uint4*>(Bp);
            rb1 = *reinterpret_cast<const uint4*>(Bp + 8 * Nn);
        }

        const int cb = i & 1;
#pragma unroll
        for (int ks2 = 0; ks2 < 16; ks2 += 8) {
            uint32_t af[4][4];
#pragma unroll
            for (int mf = 0; mf < 4; mf++) {
                int mb = wm + mf * 16;
                af[mf][0] = As[cb][ks2 + gc][mb + gr];
                af[mf][1] = As[cb][ks2 + gc][mb + gr + 8];
                af[mf][2] = As[cb][ks2 + gc + 4][mb + gr];
                af[mf][3] = As[cb][ks2 + gc + 4][mb + gr + 8];
            }
            uint32_t bf[4][2];
#pragma unroll
            for (int nf = 0; nf < 4; nf++) {
                int nb = wn + nf * 8;
                bf[nf][0] = Bs[cb][ks2 + gc][nb + gr];
                bf[nf][1] = Bs[cb][ks2 + gc + 4][nb + gr];
            }
#pragma unroll
            for (int mf = 0; mf < 4; mf++)
#pragma unroll
                for (int nf = 0; nf < 4; nf++)
                    mma_f16(acc[mf][nf], af[mf], bf[nf]);
        }

        if (i + 1 < nchunks) {
            const int nb2 = (i + 1) & 1;
            As[nb2][ak2 + 0][arow] = ra0.x; As[nb2][ak2 + 1][arow] = ra0.y;
            As[nb2][ak2 + 2][arow] = ra0.z; As[nb2][ak2 + 3][arow] = ra0.w;
            As[nb2][ak2 + 4][arow] = ra1.x; As[nb2][ak2 + 5][arow] = ra1.y;
            As[nb2][ak2 + 6][arow] = ra1.z; As[nb2][ak2 + 7][arow] = ra1.w;
            *reinterpret_cast<uint4*>(&Bs[nb2][brow][bn4]) = rb0;
            *reinterpret_cast<uint4*>(&Bs[nb2][brow + 8][bn4]) = rb1;
        }
        __syncthreads();
    }

    float* Cf = reinterpret_cast<float*>(C);
    __half* Ch = reinterpret_cast<__half*>(C);
#pragma unroll
    for (int nf = 0; nf < 4; nf++) {
        int col = bc * 128 + wn + nf * 8 + gc * 2;
        float bb0 = 0.f, bb1 = 0.f, s0 = 1.f, s1 = 1.f, h0 = 0.f, h1 = 0.f;
        if (EPI != 0) { bb0 = bias[col]; bb1 = bias[col + 1]; }
        if (EPI == 1) {
            s0 = bns[col]; s1 = bns[col + 1];
            h0 = bnsh[col]; h1 = bnsh[col + 1];
        }
#pragma unroll
        for (int mf = 0; mf < 4; mf++) {
            int row0 = br * 128 + wm + mf * 16 + gr;
            float v0 = acc[mf][nf][0], v1 = acc[mf][nf][1];
            float v2 = acc[mf][nf][2], v3 = acc[mf][nf][3];
            if (EPI != 0) { v0 += bb0; v1 += bb1; v2 += bb0; v3 += bb1; }
            if (EPI == 1 || EPI == 2) {
                v0 = fmaxf(v0, 0.f); v1 = fmaxf(v1, 0.f);
                v2 = fmaxf(v2, 0.f); v3 = fmaxf(v3, 0.f);
            }
            if (EPI == 1) {
                v0 = v0 * s0 + h0; v1 = v1 * s1 + h1;
                v2 = v2 * s0 + h0; v3 = v3 * s1 + h1;
            }
            if (OH) {
                *reinterpret_cast<__half2*>(Ch + (size_t)row0 * Nn + col) =
                    __floats2half2_rn(v0, v1);
                *reinterpret_cast<__half2*>(Ch + (size_t)(row0 + 8) * Nn + col) =
                    __floats2half2_rn(v2, v3);
            } else {
                *reinterpret_cast<float2*>(Cf + (size_t)row0 * Nn + col) = make_float2(v0, v1);
                *reinterpret_cast<float2*>(Cf + (size_t)(row0 + 8) * Nn + col) = make_float2(v2, v3);
            }
        }
    }
}

// ---------------- launch -----------------------------------------------------
extern "C" void kernel_launch(void* const* d_in, const int* in_sizes, int n_in,
                              void* d_out, int out_size) {
    const float* x   = (const float*)d_in[0];
    const int* ei    = (const int*)d_in[1];
    const int* batch = (const int*)d_in[2];
    const float* W1  = (const float*)d_in[3];  const float* b1  = (const float*)d_in[4];
    const float* W2  = (const float*)d_in[5];  const float* b2  = (const float*)d_in[6];
    const float* W3  = (const float*)d_in[7];  const float* b3  = (const float*)d_in[8];
    const float* g1  = (const float*)d_in[9];  const float* be1 = (const float*)d_in[10];
    const float* m1  = (const float*)d_in[11]; const float* v1  = (const float*)d_in[12];
    const float* g2  = (const float*)d_in[13]; const float* be2 = (const float*)d_in[14];
    const float* m2  = (const float*)d_in[15]; const float* v2  = (const float*)d_in[16];
    const float* g3  = (const float*)d_in[17]; const float* be3 = (const float*)d_in[18];
    const float* m3  = (const float*)d_in[19]; const float* v3  = (const float*)d_in[20];
    const float* Wf1 = (const float*)d_in[21]; const float* bf1 = (const float*)d_in[22];
    const float* Wf2 = (const float*)d_in[23]; const float* bf2 = (const float*)d_in[24];
    float* out = (float*)d_out;

    const int* src = ei;
    const int* dst = ei + CE;

    float *dinv, *cw, *bns, *bnsh;
    __half *xh, *agg1, *h1, *ah1, *a2, *t3, *a3, *pool, *mlp1;
    uint32_t *wp1, *wp2, *wp3, *wpf1, *wpf2;
    int *cnt, *noff, *cur, *bsum, *csrc, *gcnt, *goff, *gbsum;
    cudaGetSymbolAddress((void**)&dinv, g_dinv);
    cudaGetSymbolAddress((void**)&cnt,  g_cnt);
    cudaGetSymbolAddress((void**)&noff, g_noff);
    cudaGetSymbolAddress((void**)&cur,  g_cur);
    cudaGetSymbolAddress((void**)&bsum, g_bsum);
    cudaGetSymbolAddress((void**)&csrc, g_csrc);
    cudaGetSymbolAddress((void**)&cw,   g_cw);
    cudaGetSymbolAddress((void**)&gcnt, g_gcnt);
    cudaGetSymbolAddress((void**)&goff, g_goff);
    cudaGetSymbolAddress((void**)&gbsum, g_gbsum);
    cudaGetSymbolAddress((void**)&bns,  g_bns);
    cudaGetSymbolAddress((void**)&bnsh, g_bnsh);
    cudaGetSymbolAddress((void**)&xh,   g_xh);
    cudaGetSymbolAddress((void**)&agg1, g_agg1);
    cudaGetSymbolAddress((void**)&h1,   g_h1);
    cudaGetSymbolAddress((void**)&ah1,  g_ah1);
    cudaGetSymbolAddress((void**)&a2,   g_a2);
    cudaGetSymbolAddress((void**)&t3,   g_t3);
    cudaGetSymbolAddress((void**)&a3,   g_a3);
    cudaGetSymbolAddress((void**)&pool, g_pool);
    cudaGetSymbolAddress((void**)&mlp1, g_mlp1);
    cudaGetSymbolAddress((void**)&wp1,  g_wp1);
    cudaGetSymbolAddress((void**)&wp2,  g_wp2);
    cudaGetSymbolAddress((void**)&wp3,  g_wp3);
    cudaGetSymbolAddress((void**)&wpf1, g_wpf1);
    cudaGetSymbolAddress((void**)&wpf2, g_wpf2);

    const int T = 256;

    // ---- fused prep (wpack x5 + x->fp16 + bnprep x3 + zero) ----
    k_prep_all<<<NB_WPACK + NB_XH + NB_BN + NB_ZERO, T>>>(
        x, xh, W1, W2, W3, Wf1, Wf2, wp1, wp2, wp3, wpf1, wpf2,
        g1, be1, m1, v1, g2, be2, m2, v2, g3, be3, m3, v3, bns, bnsh,
        cnt, cur, gcnt);

    // ---- CSR build (5 launches) ----
    k_hist_all<<<(CE + CN + T - 1) / T, T>>>(dst, batch, cnt, gcnt);
    k_scan_block2<<<528, 256>>>(cnt, noff, bsum, gcnt, goff, gbsum, dinv);
    k_scan_partials2<<<2, 1024>>>(bsum, gbsum);
    k_scan_add2<<<(CN + CG + T - 1) / T, T>>>(noff, bsum, goff, gbsum);
    k_csr_scatter<<<(CE + T - 1) / T, T>>>(src, dst, dinv, noff, cur, csrc, cw);

    // ---- layer 1: aggregate x (fp16) then GEMM (bias+relu+BN1) ----
    k_agg_csr_h<DIN, false, true><<<CN / 4, 128>>>(xh, agg1, noff, csrc, cw, dinv,
                                                   nullptr, nullptr, nullptr);
    {
        dim3 grid(DH / 128, CN / 128);
        k_hgemm<1, true><<<grid, 256>>>(agg1, wp1, h1, CN, DIN, DH, b1, bns, bnsh);
    }

    // ---- layer 2 (agg-first): agg(h1) -> GEMM2 with fused bias+relu+BN2 ----
    k_agg_csr_h<DH, false, true><<<CN, 128>>>(h1, ah1, noff, csrc, cw, dinv,
                                              nullptr, nullptr, nullptr);
    {
        dim3 grid(DH / 128, CN / 128);
        k_hgemm<1, true><<<grid, 256>>>(ah1, wp2, a2, CN, DH, DH, b2,
                                        bns + DH, bnsh + DH);
    }

    // ---- layer 3: GEMM (fp16 out) then aggregate (fused BN3, fp16 out) ----
    {
        dim3 grid(DOUTD / 128, CN / 128);
        k_hgemm<0, true><<<grid, 256>>>(a2, wp3, t3, CN, DH, DOUTD, nullptr, nullptr, nullptr);
    }
    k_agg_csr_h<DOUTD, true, true><<<CN / 2, 128>>>(t3, a3, noff, csrc, cw, dinv,
                                                    b3, bns + 2 * DH, bnsh + 2 * DH);

    // ---- segment mean pool ----
    k_pool_seg<<<CG / 2, 128>>>(a3, goff, pool);

    // ---- MLP head ----
    {
        dim3 grid(DOUTD / 128, CG / 128);
        k_hgemm<2, true><<<grid, 256>>>(pool, wpf1, mlp1, CG, DOUTD, DOUTD, bf1, nullptr, nullptr);
        k_hgemm<3, false><<<grid, 256>>>(mlp1, wpf2, out, CG, DOUTD, DOUTD, bf2, nullptr, nullptr);
    }
}